// round 13
// baseline (speedup 1.0000x reference)
#include <cuda_runtime.h>
#include <cuda_fp16.h>
#include <math.h>
#include <stdint.h>

// ---------------------------------------------------------------------------
// Dims: D=512, K=8, L=64, Q=4096, C=4096.  All GEMMs on fp16 m16n8k16 mma
// (fp16 mantissa == tf32 mantissa; power-of-2 scaling keeps rounding identical
// to the validated tf32 scheme).
//   T (B-pack fp16, x2^8)  = class @ M        (3-MMA hi/lo split, ~2^-22)
//   other[q,c] = b + sum_k w_k*relu(q.Tk)     (1 MMA/k16)
//   sc  = softmax_rows(other)                 (A-pack fp16, x2^6)
//   qfp[z] = sc @ class                       (1 MMA/k16, split-K=8)
//   out = tanh((query + sum_z qfp) @ hash_w^T + b)   (fused SIMT)
// Target sm_103 (no 'a'): mma.sync/cp.async only.
// All mma kernels: 256 threads (8 warps, 2m x 4n, warp tile 64x32),
// 6-stage x 32KB cp.async pipelines (prefetch distance 5).
// ---------------------------------------------------------------------------

__device__ __half g_T16[(size_t)8 * 4096 * 512];   // T, B-pack, x2^8 (32MB)
__device__ float  g_other[(size_t)4096 * 4096];    // logits fp32 (64MB)
__device__ __half g_sc16[(size_t)4096 * 4096];     // scores A-pack x2^6 (32MB)
__device__ __half g_q16[(size_t)4096 * 512];       // query A-pack x2^8
__device__ __half g_cah[(size_t)4096 * 512];       // class A-pack hi (x2^8)
__device__ __half g_cal[(size_t)4096 * 512];       // class A-pack lo
__device__ __half g_mbh[(size_t)4096 * 512];       // M^T B-pack hi (x2^10)
__device__ __half g_mbl[(size_t)4096 * 512];       // M^T B-pack lo
__device__ __half g_cbh[(size_t)512 * 4096];       // class^T B-pack (x2^8)
__device__ float  g_qfp[(size_t)8 * 4096 * 512];   // split-K partials (64MB)
__device__ float  g_hwT[512 * 64];

// ------------------------------ helpers -----------------------------------
__device__ __forceinline__ uint32_t smem_u32(const void* p) {
    uint32_t a;
    asm("{ .reg .u64 t; cvta.to.shared.u64 t, %1; cvt.u32.u64 %0, t; }" : "=r"(a) : "l"(p));
    return a;
}
__device__ __forceinline__ void mma_f16(float* c, const uint32_t* a, const uint32_t* b) {
    asm volatile(
        "mma.sync.aligned.m16n8k16.row.col.f32.f16.f16.f32 "
        "{%0,%1,%2,%3}, {%4,%5,%6,%7}, {%8,%9}, {%0,%1,%2,%3};"
        : "+f"(c[0]), "+f"(c[1]), "+f"(c[2]), "+f"(c[3])
        : "r"(a[0]), "r"(a[1]), "r"(a[2]), "r"(a[3]), "r"(b[0]), "r"(b[1]));
}
#define CPA(dst, src) \
    asm volatile("cp.async.cg.shared.global [%0], [%1], 16;" :: "r"(dst), "l"(src))
#define CPA_COMMIT() asm volatile("cp.async.commit_group;" ::: "memory")
#define CPA_WAIT4()  asm volatile("cp.async.wait_group 4;" ::: "memory")

// packed offsets (64-k chunk granularity), element (m|n, k), reduction Ktot
__device__ __forceinline__ size_t apack16(int m, int k, int Ktot) {
    return ((size_t)(m >> 7) * (Ktot >> 6) + (k >> 6)) * 8192
         + (size_t)(((((m >> 4) & 7) << 2) + ((k >> 4) & 3)) * 256
         + (((m & 7) << 2) + ((k & 7) >> 1)) * 8
         + (((k >> 3) & 1) << 2) + (((m >> 3) & 1) << 1) + (k & 1));
}
__device__ __forceinline__ size_t bpack16(int n, int k, int Ktot) {
    return ((size_t)(n >> 7) * (Ktot >> 6) + (k >> 6)) * 8192
         + (size_t)(((((n >> 3) & 15) << 2) + ((k >> 4) & 3)) * 128
         + (((n & 7) << 2) + ((k & 7) >> 1)) * 4
         + (((k >> 3) & 1) << 1) + (k & 1));
}

// ---------------------------------------------------------------------------
// Stage 1: T = class @ M, hi/lo split (3 MMA/k16). 32-k sub-chunks (32KB:
// Ah/Al/Bh/Bl 8KB each), 6 stages. Scatter epilogue to T16 B-pack.
// ---------------------------------------------------------------------------
#define G1_SF 16384   // halves per stage (32KB)

__global__ void __launch_bounds__(256, 1)
gemm_split_f16(const __half* __restrict__ Ah, const __half* __restrict__ Al,
               const __half* __restrict__ Bh, const __half* __restrict__ Bl,
               __half* __restrict__ outh)
{
    extern __shared__ char smc[];
    __half* sm = (__half*)smc;

    const int tid = threadIdx.x;
    const int lane = tid & 31;
    const int wid = tid >> 5;
    const int wm = wid >> 2;   // 0..1
    const int wn = wid & 3;    // 0..3
    const int m0 = blockIdx.y * 128;
    const int n0 = blockIdx.x * 128;
    const int NCH = 16;        // 512 k / 32

    const size_t aBlk = (size_t)(m0 >> 7) * 8 * 8192;
    const size_t bBlk = (size_t)(n0 >> 7) * 8 * 8192;

    float macc[4][4][4];
#pragma unroll
    for (int mi = 0; mi < 4; mi++)
#pragma unroll
        for (int ni = 0; ni < 4; ni++)
#pragma unroll
            for (int r = 0; r < 4; r++) macc[mi][ni][r] = 0.0f;

    auto issue = [&](int it, int s) {
        const int c64 = it >> 1, p = it & 1;
        const size_t b64 = (size_t)c64 * 8192;
        const uint32_t smb = smem_u32(sm + s * G1_SF);
        // A runs: mfrag q blocks of 512 halves at q*1024 + p*512
        {
            const int q = tid >> 6;
            const int r = (tid & 63) * 8;
            const size_t s0 = aBlk + b64 + (size_t)q * 1024 + p * 512 + r;
            const uint32_t d0 = smb + tid * 16;
            CPA(d0,                Ah + s0);
            CPA(d0 + 4096,         Ah + s0 + 4096);
            CPA(d0 + 8192,         Al + s0);
            CPA(d0 + 8192 + 4096,  Al + s0 + 4096);
        }
        // B runs: nfrag blocks of 256 halves at run*512 + p*256
        {
            const int run = tid >> 5;
            const int r = (tid & 31) * 8;
            const size_t s0 = bBlk + b64 + (size_t)run * 512 + p * 256 + r;
            const uint32_t d0 = smb + 16384 + tid * 16;
            CPA(d0,                Bh + s0);
            CPA(d0 + 4096,         Bh + s0 + 4096);
            CPA(d0 + 8192,         Bl + s0);
            CPA(d0 + 8192 + 4096,  Bl + s0 + 4096);
        }
        CPA_COMMIT();
    };

#pragma unroll
    for (int i = 0; i < 5; i++) issue(i, i);

    int s = 0;
#pragma unroll 1
    for (int it = 0; it < NCH; it++) {
        CPA_WAIT4();
        __syncthreads();
        if (it + 5 < NCH) {
            int s2 = s + 5; if (s2 >= 6) s2 -= 6;
            issue(it + 5, s2);
        } else {
            CPA_COMMIT();   // empty group keeps the count invariant
        }

        const __half* pa  = sm + s * G1_SF;
        const __half* pal = pa + 4096;
        const __half* pbh = pa + 8192;
        const __half* pbl = pa + 12288;
#pragma unroll
        for (int kf = 0; kf < 2; kf++) {
            uint4 ah[4], al[4];
            uint2 bh[4], bl[4];
#pragma unroll
            for (int mi = 0; mi < 4; mi++) {
                int ao = (wm * 4 + mi) * 512 + kf * 256 + lane * 8;
                ah[mi] = *(const uint4*)(pa + ao);
                al[mi] = *(const uint4*)(pal + ao);
            }
#pragma unroll
            for (int ni = 0; ni < 4; ni++) {
                int bo = (wn * 4 + ni) * 256 + kf * 128 + lane * 4;
                bh[ni] = *(const uint2*)(pbh + bo);
                bl[ni] = *(const uint2*)(pbl + bo);
            }
#pragma unroll
            for (int mi = 0; mi < 4; mi++)
#pragma unroll
                for (int ni = 0; ni < 4; ni++)
                    mma_f16(macc[mi][ni], (const uint32_t*)&ah[mi], (const uint32_t*)&bh[ni]);
#pragma unroll
            for (int mi = 0; mi < 4; mi++)
#pragma unroll
                for (int ni = 0; ni < 4; ni++)
                    mma_f16(macc[mi][ni], (const uint32_t*)&al[mi], (const uint32_t*)&bh[ni]);
#pragma unroll
            for (int mi = 0; mi < 4; mi++)
#pragma unroll
                for (int ni = 0; ni < 4; ni++)
                    mma_f16(macc[mi][ni], (const uint32_t*)&ah[mi], (const uint32_t*)&bl[ni]);
        }
        if (++s >= 6) s -= 6;
    }

    // epilogue: A x2^8 * B x2^10 -> T x2^8 => *2^-10
    const int lq = lane >> 2;
    const int ld = lane & 3;
    const float ds = 0.0009765625f;
#pragma unroll
    for (int mi = 0; mi < 4; mi++) {
        const int r = m0 + wm * 64 + mi * 16 + lq;
#pragma unroll
        for (int ni = 0; ni < 4; ni++) {
            const int c = n0 + wn * 32 + ni * 8 + 2 * ld;
#pragma unroll
            for (int rr = 0; rr < 4; rr++) {
                int row = r + (rr >> 1) * 8;
                int col = c + (rr & 1);
                int kp = col & 7, dd = col >> 3;
                outh[(size_t)kp * 2097152 + bpack16(row, dd, 512)] =
                    __float2half_rn(macc[mi][ni][rr] * ds);
            }
        }
    }
}

// ---------------------------------------------------------------------------
// Stage 4: qfp[z] = sc @ class^T (single fp16, 1 MMA/k16). 64-k chunks (32KB),
// 6 stages, split-K via blockIdx.z.
// ---------------------------------------------------------------------------
#define G4_SF 16384

__global__ void __launch_bounds__(256, 1)
gemm_single_f16(const __half* __restrict__ Ah, const __half* __restrict__ Bh,
                float* __restrict__ out, int Ktot, int kseg)
{
    extern __shared__ char smc[];
    __half* sm = (__half*)smc;

    const int tid = threadIdx.x;
    const int lane = tid & 31;
    const int wid = tid >> 5;
    const int wm = wid >> 2;
    const int wn = wid & 3;
    const int m0 = blockIdx.y * 128;
    const int n0 = blockIdx.x * 128;
    const int kstart = blockIdx.z * kseg;
    const int NCH = kseg / 64;

    const size_t aBlk = ((size_t)(m0 >> 7) * (Ktot >> 6) + (kstart >> 6)) * 8192;
    const size_t bBlk = ((size_t)(n0 >> 7) * (Ktot >> 6) + (kstart >> 6)) * 8192;

    float macc[4][4][4];
#pragma unroll
    for (int mi = 0; mi < 4; mi++)
#pragma unroll
        for (int ni = 0; ni < 4; ni++)
#pragma unroll
            for (int r = 0; r < 4; r++) macc[mi][ni][r] = 0.0f;

    auto issue = [&](int it, int s) {
        const size_t cofs = (size_t)it * 8192 + tid * 8;
        const uint32_t da = smem_u32(sm + s * G4_SF) + tid * 16;
#pragma unroll
        for (int p = 0; p < 4; p++) {
            CPA(da + p * 4096,         Ah + aBlk + cofs + p * 2048);
            CPA(da + 16384 + p * 4096, Bh + bBlk + cofs + p * 2048);
        }
        CPA_COMMIT();
    };

    for (int i = 0; i < 5; i++) if (i < NCH) issue(i, i); else CPA_COMMIT();

    int s = 0;
#pragma unroll 1
    for (int it = 0; it < NCH; it++) {
        CPA_WAIT4();
        __syncthreads();
        if (it + 5 < NCH) {
            int s2 = s + 5; if (s2 >= 6) s2 -= 6;
            issue(it + 5, s2);
        } else {
            CPA_COMMIT();
        }

        const __half* pa = sm + s * G4_SF;
        const __half* pb = pa + 8192;
#pragma unroll
        for (int kk = 0; kk < 4; kk++) {
            uint4 a[4];
            uint2 b[4];
#pragma unroll
            for (int mi = 0; mi < 4; mi++)
                a[mi] = *(const uint4*)(pa + (((wm * 4 + mi) * 4 + kk) << 8) + lane * 8);
#pragma unroll
            for (int ni = 0; ni < 4; ni++)
                b[ni] = *(const uint2*)(pb + (((wn * 4 + ni) * 4 + kk) << 7) + lane * 4);
#pragma unroll
            for (int mi = 0; mi < 4; mi++)
#pragma unroll
                for (int ni = 0; ni < 4; ni++)
                    mma_f16(macc[mi][ni], (const uint32_t*)&a[mi], (const uint32_t*)&b[ni]);
        }
        if (++s >= 6) s -= 6;
    }

    // sc x2^6 * class x2^8 -> *2^-14
    const int lq = lane >> 2;
    const int ld = lane & 3;
    const float ds = 6.103515625e-05f;
    float* ob = out + (size_t)blockIdx.z * 4096 * 512;
#pragma unroll
    for (int mi = 0; mi < 4; mi++) {
        const int r = m0 + wm * 64 + mi * 16 + lq;
#pragma unroll
        for (int ni = 0; ni < 4; ni++) {
            const int c = n0 + wn * 32 + ni * 8 + 2 * ld;
            *(float2*)(ob + (size_t)r * 512 + c) =
                make_float2(macc[mi][ni][0] * ds, macc[mi][ni][1] * ds);
            *(float2*)(ob + (size_t)(r + 8) * 512 + c) =
                make_float2(macc[mi][ni][2] * ds, macc[mi][ni][3] * ds);
        }
    }
}

// ---------------------------------------------------------------------------
// Stage 2: fused bilinear + relu + score. 64-d chunks (32KB), 6 stages.
// it = k*8 + t.
// ---------------------------------------------------------------------------
#define S2_SF 16384

__global__ void __launch_bounds__(256, 1)
stage2_f16(const __half* __restrict__ q16, const __half* __restrict__ T16,
           const float* __restrict__ score_w, const float* __restrict__ score_b,
           float* __restrict__ other)
{
    extern __shared__ char smc[];
    __half* sm = (__half*)smc;
    const int tid = threadIdx.x;
    const int lane = tid & 31;
    const int wid = tid >> 5;
    const int wm = wid >> 2;
    const int wn = wid & 3;
    const int q0 = blockIdx.y * 128;
    const int c0 = blockIdx.x * 128;

    const size_t aBase = (size_t)(q0 >> 7) * 8 * 8192;
    const size_t bBase = (size_t)(c0 >> 7) * 8 * 8192;

    float sacc[4][4][4];
#pragma unroll
    for (int mi = 0; mi < 4; mi++)
#pragma unroll
        for (int ni = 0; ni < 4; ni++)
#pragma unroll
            for (int r = 0; r < 4; r++) sacc[mi][ni][r] = 0.0f;

    auto issue = [&](int it, int s) {
        const int k = it >> 3, t = it & 7;
        const __half* srcA = q16 + aBase + (size_t)t * 8192 + tid * 8;
        const __half* srcB = T16 + (size_t)k * 2097152 + bBase + (size_t)t * 8192 + tid * 8;
        const uint32_t da = smem_u32(sm + s * S2_SF) + tid * 16;
#pragma unroll
        for (int p = 0; p < 4; p++) {
            CPA(da + p * 4096,         srcA + p * 2048);
            CPA(da + 16384 + p * 4096, srcB + p * 2048);
        }
        CPA_COMMIT();
    };

#pragma unroll
    for (int i = 0; i < 5; i++) issue(i, i);

    float macc[4][4][4];
    int s = 0;
#pragma unroll 1
    for (int it = 0; it < 64; it++) {
        const int k = it >> 3, t = it & 7;
        if (t == 0) {
#pragma unroll
            for (int mi = 0; mi < 4; mi++)
#pragma unroll
                for (int ni = 0; ni < 4; ni++)
#pragma unroll
                    for (int r = 0; r < 4; r++) macc[mi][ni][r] = 0.0f;
        }

        CPA_WAIT4();
        __syncthreads();
        if (it + 5 < 64) {
            int s2 = s + 5; if (s2 >= 6) s2 -= 6;
            issue(it + 5, s2);
        } else {
            CPA_COMMIT();
        }

        const __half* pa = sm + s * S2_SF;
        const __half* pb = pa + 8192;
#pragma unroll
        for (int kk = 0; kk < 4; kk++) {
            uint4 a[4];
            uint2 b[4];
#pragma unroll
            for (int mi = 0; mi < 4; mi++)
                a[mi] = *(const uint4*)(pa + (((wm * 4 + mi) * 4 + kk) << 8) + lane * 8);
#pragma unroll
            for (int ni = 0; ni < 4; ni++)
                b[ni] = *(const uint2*)(pb + (((wn * 4 + ni) * 4 + kk) << 7) + lane * 4);
#pragma unroll
            for (int mi = 0; mi < 4; mi++)
#pragma unroll
                for (int ni = 0; ni < 4; ni++)
                    mma_f16(macc[mi][ni], (const uint32_t*)&a[mi], (const uint32_t*)&b[ni]);
        }

        if (t == 7) {
            // acc = P * 2^16 (q x2^8, T x2^8): fold 2^-16 into w
            const float w = __ldg(score_w + k) * 1.52587890625e-05f;
#pragma unroll
            for (int mi = 0; mi < 4; mi++)
#pragma unroll
                for (int ni = 0; ni < 4; ni++)
#pragma unroll
                    for (int r = 0; r < 4; r++)
                        sacc[mi][ni][r] = fmaf(fmaxf(macc[mi][ni][r], 0.0f), w,
                                               sacc[mi][ni][r]);
        }
        if (++s >= 6) s -= 6;
    }

    const int lq = lane >> 2;
    const int ld = lane & 3;
    const float sb = __ldg(score_b);
#pragma unroll
    for (int mi = 0; mi < 4; mi++) {
        const int q = q0 + wm * 64 + mi * 16 + lq;
#pragma unroll
        for (int ni = 0; ni < 4; ni++) {
            const int c = c0 + wn * 32 + ni * 8 + 2 * ld;
            *(float2*)(other + (size_t)q * 4096 + c) =
                make_float2(sb + sacc[mi][ni][0], sb + sacc[mi][ni][1]);
            *(float2*)(other + (size_t)(q + 8) * 4096 + c) =
                make_float2(sb + sacc[mi][ni][2], sb + sacc[mi][ni][3]);
        }
    }
}

// ---------------------------------------------------------------------------
// Softmax (paired rows q, q+8); fp16 A-pack output (Ktot=4096, x2^6).
// Thread handles 16 consecutive columns -> one contiguous 64B packed block.
// ---------------------------------------------------------------------------
__global__ void softmax_pack2(const float* __restrict__ o, __half* __restrict__ sc)
{
    const int b = blockIdx.x;
    const int qa = ((b >> 3) << 4) | (b & 7);
    const int tid = threadIdx.x;

    float v0[16], v1[16];
    {
        const float4* p0 = (const float4*)(o + (size_t)qa * 4096) + tid * 4;
        const float4* p1 = (const float4*)(o + (size_t)(qa + 8) * 4096) + tid * 4;
#pragma unroll
        for (int i = 0; i < 4; i++) {
            float4 x = p0[i];
            v0[i * 4] = x.x; v0[i * 4 + 1] = x.y; v0[i * 4 + 2] = x.z; v0[i * 4 + 3] = x.w;
            float4 y = p1[i];
            v1[i * 4] = y.x; v1[i * 4 + 1] = y.y; v1[i * 4 + 2] = y.z; v1[i * 4 + 3] = y.w;
        }
    }
    float mx0 = -1e30f, mx1 = -1e30f;
#pragma unroll
    for (int i = 0; i < 16; i++) { mx0 = fmaxf(mx0, v0[i]); mx1 = fmaxf(mx1, v1[i]); }

    __shared__ float sm0[8], sm1[8];
#pragma unroll
    for (int o2 = 16; o2 > 0; o2 >>= 1) {
        mx0 = fmaxf(mx0, __shfl_xor_sync(0xffffffffu, mx0, o2));
        mx1 = fmaxf(mx1, __shfl_xor_sync(0xffffffffu, mx1, o2));
    }
    if ((tid & 31) == 0) { sm0[tid >> 5] = mx0; sm1[tid >> 5] = mx1; }
    __syncthreads();
    mx0 = sm0[0]; mx1 = sm1[0];
#pragma unroll
    for (int i = 1; i < 8; i++) { mx0 = fmaxf(mx0, sm0[i]); mx1 = fmaxf(mx1, sm1[i]); }
    __syncthreads();

    float s0 = 0.0f, s1 = 0.0f;
#pragma unroll
    for (int i = 0; i < 16; i++) {
        v0[i] = expf(v0[i] - mx0); s0 += v0[i];
        v1[i] = expf(v1[i] - mx1); s1 += v1[i];
    }
#pragma unroll
    for (int o2 = 16; o2 > 0; o2 >>= 1) {
        s0 += __shfl_xor_sync(0xffffffffu, s0, o2);
        s1 += __shfl_xor_sync(0xffffffffu, s1, o2);
    }
    if ((tid & 31) == 0) { sm0[tid >> 5] = s0; sm1[tid >> 5] = s1; }
    __syncthreads();
    s0 = 0.0f; s1 = 0.0f;
#pragma unroll
    for (int i = 0; i < 8; i++) { s0 += sm0[i]; s1 += sm1[i]; }
    const float i0 = 64.0f / s0, i1 = 64.0f / s1;   // fold x2^6 scale

    __half hbuf[32];
#pragma unroll
    for (int j = 0; j < 32; j++) {
        int t2 = j >> 3, kb3 = (j >> 2) & 1, mrow = (j >> 1) & 1, h = j & 1;
        int kl = kb3 * 8 + t2 * 2 + h;
        hbuf[j] = __float2half_rn(mrow ? v1[kl] * i1 : v0[kl] * i0);
    }
    __half* dst = sc + apack16(qa, tid * 16, 4096);
#pragma unroll
    for (int j = 0; j < 4; j++)
        *(uint4*)(dst + j * 8) = *(const uint4*)(hbuf + j * 8);
}

// ---------------------------------------------------------------------------
// Fused stage 5: qf = query + sum_z qfp[z] (smem), out = tanh(qf @ hwT + b).
// ---------------------------------------------------------------------------
__global__ void __launch_bounds__(256, 2)
stage5_fused(const float* __restrict__ query, const float* __restrict__ qfp,
             const float* __restrict__ hwT, const float* __restrict__ hash_b,
             float* __restrict__ out)
{
    __shared__ float qf_s[16 * 512];
    const int tid = threadIdx.x;
    const int qbase = blockIdx.x * 16;
    const size_t S = (size_t)4096 * 512;
    const size_t gbase = (size_t)qbase * 512;

#pragma unroll
    for (int j = 0; j < 8; j++) {
        int i4 = tid + j * 256;
        size_t g = gbase + (size_t)i4 * 4;
        float4 acc = *(const float4*)(query + g);
#pragma unroll
        for (int z = 0; z < 8; z++) {
            float4 p = *(const float4*)(qfp + z * S + g);
            acc.x += p.x; acc.y += p.y; acc.z += p.z; acc.w += p.w;
        }
        *(float4*)(qf_s + i4 * 4) = acc;
    }
    __syncthreads();

    const int q = tid >> 4;
    const int lb = (tid & 15) * 4;
    float a0 = 0, a1 = 0, a2 = 0, a3 = 0;
    const float* qr = qf_s + q * 512;
#pragma unroll 4
    for (int d = 0; d < 512; d += 4) {
        float4 qv = *(const float4*)(qr + d);
        float4 h0 = __ldg((const float4*)(hwT + (size_t)d * 64 + lb));
        float4 h1 = __ldg((const float4*)(hwT + (size_t)(d + 1) * 64 + lb));
        float4 h2 = __ldg((const float4*)(hwT + (size_t)(d + 2) * 64 + lb));
        float4 h3 = __ldg((const float4*)(hwT + (size_t)(d + 3) * 64 + lb));
        a0 = fmaf(qv.x, h0.x, fmaf(qv.y, h1.x, fmaf(qv.z, h2.x, fmaf(qv.w, h3.x, a0))));
        a1 = fmaf(qv.x, h0.y, fmaf(qv.y, h1.y, fmaf(qv.z, h2.y, fmaf(qv.w, h3.y, a1))));
        a2 = fmaf(qv.x, h0.z, fmaf(qv.y, h1.z, fmaf(qv.z, h2.z, fmaf(qv.w, h3.z, a2))));
        a3 = fmaf(qv.x, h0.w, fmaf(qv.y, h1.w, fmaf(qv.z, h2.w, fmaf(qv.w, h3.w, a3))));
    }
    float4 hb = __ldg((const float4*)(hash_b + lb));
    float4 r = make_float4(tanhf(a0 + hb.x), tanhf(a1 + hb.y),
                           tanhf(a2 + hb.z), tanhf(a3 + hb.w));
    *(float4*)(out + (size_t)(qbase + q) * 64 + lb) = r;
}

// ---------------------------------------------------------------------------
// Prep kernels
// ---------------------------------------------------------------------------
__global__ void transpose_hw(const float* __restrict__ hw)
{
    int idx = blockIdx.x * blockDim.x + threadIdx.x;
    int l = idx >> 9;
    int d = idx & 511;
    g_hwT[d * 64 + l] = hw[idx];
}

// query -> A-pack fp16 x2^8. Thread handles rows (m, m+8) x 16 k -> 64B store.
__global__ void pack_q16(const float* __restrict__ q)
{
    int t = blockIdx.x * blockDim.x + threadIdx.x;
    int kg = t & 31;
    int pr = t >> 5;
    int m0 = ((pr >> 3) << 4) | (pr & 7);
    int kb = kg * 16;

    float v0[16], v1[16];
    const float4* p0 = (const float4*)(q + (size_t)m0 * 512 + kb);
    const float4* p1 = (const float4*)(q + (size_t)(m0 + 8) * 512 + kb);
#pragma unroll
    for (int i = 0; i < 4; i++) {
        float4 x = p0[i];
        v0[i*4] = x.x; v0[i*4+1] = x.y; v0[i*4+2] = x.z; v0[i*4+3] = x.w;
        float4 y = p1[i];
        v1[i*4] = y.x; v1[i*4+1] = y.y; v1[i*4+2] = y.z; v1[i*4+3] = y.w;
    }
    __half hbuf[32];
#pragma unroll
    for (int j = 0; j < 32; j++) {
        int t2 = j >> 3, kb3 = (j >> 2) & 1, mrow = (j >> 1) & 1, h = j & 1;
        int kl = kb3 * 8 + t2 * 2 + h;
        hbuf[j] = __float2half_rn((mrow ? v1[kl] : v0[kl]) * 256.0f);
    }
    __half* dst = g_q16 + apack16(m0, kb, 512);
#pragma unroll
    for (int j = 0; j < 4; j++)
        *(uint4*)(dst + j * 8) = *(const uint4*)(hbuf + j * 8);
}

// class -> A-pack fp16 hi/lo x2^8
__global__ void pack_classA16(const float* __restrict__ cv)
{
    int t = blockIdx.x * blockDim.x + threadIdx.x;
    int kg = t & 31;
    int pr = t >> 5;
    int m0 = ((pr >> 3) << 4) | (pr & 7);
    int kb = kg * 16;

    float v0[16], v1[16];
    const float4* p0 = (const float4*)(cv + (size_t)m0 * 512 + kb);
    const float4* p1 = (const float4*)(cv + (size_t)(m0 + 8) * 512 + kb);
#pragma unroll
    for (int i = 0; i < 4; i++) {
        float4 x = p0[i];
        v0[i*4] = x.x; v0[i*4+1] = x.y; v0[i*4+2] = x.z; v0[i*4+3] = x.w;
        float4 y = p1[i];
        v1[i*4] = y.x; v1[i*4+1] = y.y; v1[i*4+2] = y.z; v1[i*4+3] = y.w;
    }
    __half hb[32], lb[32];
#pragma unroll
    for (int j = 0; j < 32; j++) {
        int t2 = j >> 3, kb3 = (j >> 2) & 1, mrow = (j >> 1) & 1, h = j & 1;
        int kl = kb3 * 8 + t2 * 2 + h;
        float v = (mrow ? v1[kl] : v0[kl]) * 256.0f;
        __half hi = __float2half_rn(v);
        hb[j] = hi;
        lb[j] = __float2half_rn(v - __half2float(hi));
    }
    size_t off = apack16(m0, kb, 512);
#pragma unroll
    for (int j = 0; j < 4; j++) {
        *(uint4*)(g_cah + off + j * 8) = *(const uint4*)(hb + j * 8);
        *(uint4*)(g_cal + off + j * 8) = *(const uint4*)(lb + j * 8);
    }
}

// in [R][C] (R=k-dim, C=n-dim) -> B-pack fp16 hi/lo, one thread per 16-k group.
__global__ void pack_B16_split(const float* __restrict__ in,
                               __half* __restrict__ ohi, __half* __restrict__ olo,
                               int R, int C, float scale)
{
    unsigned tt = blockIdx.x * blockDim.x + threadIdx.x;
    unsigned k16 = tt / (unsigned)C;
    unsigned n = tt - k16 * (unsigned)C;
    int kb = (int)k16 * 16;

    unsigned short h[16], l[16];
#pragma unroll
    for (int i = 0; i < 16; i++) {
        float v = in[(size_t)(kb + i) * C + n] * scale;
        __half hv = __float2half_rn(v);
        h[i] = __half_as_ushort(hv);
        l[i] = __half_as_ushort(__float2half_rn(v - __half2float(hv)));
    }
    size_t base = bpack16((int)n, kb, R);
    const int map[16] = {0,1,8,9,2,3,10,11,4,5,12,13,6,7,14,15};
    uint32_t uh[8], ul[8];
#pragma unroll
    for (int j = 0; j < 8; j++) {
        uh[j] = (uint32_t)h[map[2*j]] | ((uint32_t)h[map[2*j+1]] << 16);
        ul[j] = (uint32_t)l[map[2*j]] | ((uint32_t)l[map[2*j+1]] << 16);
    }
    *(uint4*)(ohi + base)     = make_uint4(uh[0], uh[1], uh[2], uh[3]);
    *(uint4*)(ohi + base + 8) = make_uint4(uh[4], uh[5], uh[6], uh[7]);
    *(uint4*)(olo + base)     = make_uint4(ul[0], ul[1], ul[2], ul[3]);
    *(uint4*)(olo + base + 8) = make_uint4(ul[4], ul[5], ul[6], ul[7]);
}

// class^T -> B-pack fp16 single x2^8 (N=512 d-dim, K=4096 c-dim)
__global__ void pack_classB16(const float* __restrict__ cv)
{
    unsigned tt = blockIdx.x * blockDim.x + threadIdx.x;
    unsigned c16 = tt / 512u;
    unsigned d = tt - c16 * 512u;
    int cb = (int)c16 * 16;

    unsigned short h[16];
#pragma unroll
    for (int i = 0; i < 16; i++)
        h[i] = __half_as_ushort(__float2half_rn(cv[(size_t)(cb + i) * 512 + d] * 256.0f));
    size_t base = bpack16((int)d, cb, 4096);
    const int map[16] = {0,1,8,9,2,3,10,11,4,5,12,13,6,7,14,15};
    uint32_t u[8];
#pragma unroll
    for (int j = 0; j < 8; j++)
        u[j] = (uint32_t)h[map[2*j]] | ((uint32_t)h[map[2*j+1]] << 16);
    *(uint4*)(g_cbh + base)     = make_uint4(u[0], u[1], u[2], u[3]);
    *(uint4*)(g_cbh + base + 8) = make_uint4(u[4], u[5], u[6], u[7]);
}

// ---------------------------------------------------------------------------
extern "C" void kernel_launch(void* const* d_in, const int* in_sizes, int n_in,
                              void* d_out, int out_size)
{
    const float* class_v = (const float*)d_in[0];
    const float* query_v = (const float*)d_in[1];
    const float* Mmat    = (const float*)d_in[2];
    const float* score_w = (const float*)d_in[3];
    const float* score_b = (const float*)d_in[4];
    const float* hash_w  = (const float*)d_in[5];
    const float* hash_b  = (const float*)d_in[6];
    float* out = (float*)d_out;

    float *other, *qfp, *hwT;
    __half *T16, *sc16, *q16, *cah, *cal, *mbh, *mbl, *cbh;
    cudaGetSymbolAddress((void**)&T16, g_T16);
    cudaGetSymbolAddress((void**)&other, g_other);
    cudaGetSymbolAddress((void**)&sc16, g_sc16);
    cudaGetSymbolAddress((void**)&q16, g_q16);
    cudaGetSymbolAddress((void**)&cah, g_cah);
    cudaGetSymbolAddress((void**)&cal, g_cal);
    cudaGetSymbolAddress((void**)&mbh, g_mbh);
    cudaGetSymbolAddress((void**)&mbl, g_mbl);
    cudaGetSymbolAddress((void**)&cbh, g_cbh);
    cudaGetSymbolAddress((void**)&qfp, g_qfp);
    cudaGetSymbolAddress((void**)&hwT, g_hwT);

    const int PIPE_SMEM = 6 * 32768;   // 196608 B, all mma kernels
    cudaFuncSetAttribute(stage2_f16, cudaFuncAttributeMaxDynamicSharedMemorySize, PIPE_SMEM);
    cudaFuncSetAttribute(gemm_split_f16, cudaFuncAttributeMaxDynamicSharedMemorySize, PIPE_SMEM);
    cudaFuncSetAttribute(gemm_single_f16, cudaFuncAttributeMaxDynamicSharedMemorySize, PIPE_SMEM);

    // prep
    pack_q16<<<256, 256>>>(query_v);
    pack_classA16<<<256, 256>>>(class_v);
    pack_B16_split<<<512, 256>>>(Mmat, mbh, mbl, 512, 4096, 1024.0f);  // M x2^10

    // Stage 1: T = class @ M  (fp16 3-MMA split, scatter to B-pack)
    gemm_split_f16<<<dim3(32, 32), 256, PIPE_SMEM>>>(cah, cal, mbh, mbl, T16);

    pack_classB16<<<512, 256>>>(class_v);

    // Stage 2: fused bilinear + relu + score (fp16, 1 MMA/k16)
    stage2_f16<<<dim3(32, 32), 256, PIPE_SMEM>>>(q16, T16, score_w, score_b, other);

    // Stage 3: softmax -> fp16 packed scores
    softmax_pack2<<<2048, 256>>>(other, sc16);

    // Stage 4: qf partials = sc @ class (fp16 single, split-K=8)
    gemm_single_f16<<<dim3(4, 32, 8), 256, PIPE_SMEM>>>(sc16, cbh, qfp, 4096, 512);

    transpose_hw<<<128, 256>>>(hash_w);

    // Stage 5 (fused reduce + residual + tanh GEMM)
    stage5_fused<<<256, 256>>>(query_v, qfp, hwT, hash_b, out);
}

// round 15
// speedup vs baseline: 1.0853x; 1.0853x over previous
#include <cuda_runtime.h>
#include <cuda_fp16.h>
#include <math.h>
#include <stdint.h>

// ---------------------------------------------------------------------------
// Dims: D=512, K=8, L=64, Q=4096, C=4096.  All GEMMs on fp16 m16n8k16 mma
// (fp16 mantissa == tf32 mantissa; power-of-2 scaling keeps rounding identical
// to the validated tf32 scheme).
//   T (B-pack fp16, x2^8)  = class @ M        (3-MMA hi/lo split, ~2^-22)
//   other[q,c] = b + sum_k w_k*relu(q.Tk)     (1 MMA/k16)
//   sc  = softmax_rows(other)                 (A-pack fp16, x2^6)
//   qfp[z] = sc @ class                       (1 MMA/k16, split-K=8)
//   out = tanh((query + sum_z qfp) @ hash_w^T + b)   (fused SIMT)
// Target sm_103 (no 'a'): mma.sync/cp.async only.
// stage1/stage4: 96KB smem + launch_bounds(256,2) -> 2 CTAs/SM.
// stage2: R11 shape (1 CTA, 192KB, 8-cp.async issue loop — R14's bug fixed).
// ---------------------------------------------------------------------------

__device__ __half g_T16[(size_t)8 * 4096 * 512];   // T, B-pack, x2^8 (32MB)
__device__ float  g_other[(size_t)4096 * 4096];    // logits fp32 (64MB)
__device__ __half g_sc16[(size_t)4096 * 4096];     // scores A-pack x2^6 (32MB)
__device__ __half g_q16[(size_t)4096 * 512];       // query A-pack x2^8
__device__ __half g_cah[(size_t)4096 * 512];       // class A-pack hi (x2^8)
__device__ __half g_cal[(size_t)4096 * 512];       // class A-pack lo
__device__ __half g_mbh[(size_t)4096 * 512];       // M^T B-pack hi (x2^10)
__device__ __half g_mbl[(size_t)4096 * 512];       // M^T B-pack lo
__device__ __half g_cbh[(size_t)512 * 4096];       // class^T B-pack (x2^8)
__device__ float  g_qfp[(size_t)8 * 4096 * 512];   // split-K partials (64MB)
__device__ float  g_hwT[512 * 64];

// ------------------------------ helpers -----------------------------------
__device__ __forceinline__ uint32_t smem_u32(const void* p) {
    uint32_t a;
    asm("{ .reg .u64 t; cvta.to.shared.u64 t, %1; cvt.u32.u64 %0, t; }" : "=r"(a) : "l"(p));
    return a;
}
__device__ __forceinline__ void mma_f16(float* c, const uint32_t* a, const uint32_t* b) {
    asm volatile(
        "mma.sync.aligned.m16n8k16.row.col.f32.f16.f16.f32 "
        "{%0,%1,%2,%3}, {%4,%5,%6,%7}, {%8,%9}, {%0,%1,%2,%3};"
        : "+f"(c[0]), "+f"(c[1]), "+f"(c[2]), "+f"(c[3])
        : "r"(a[0]), "r"(a[1]), "r"(a[2]), "r"(a[3]), "r"(b[0]), "r"(b[1]));
}
#define CPA(dst, src) \
    asm volatile("cp.async.cg.shared.global [%0], [%1], 16;" :: "r"(dst), "l"(src))
#define CPA_COMMIT() asm volatile("cp.async.commit_group;" ::: "memory")
#define CPA_WAIT1()  asm volatile("cp.async.wait_group 1;" ::: "memory")
#define CPA_WAIT0()  asm volatile("cp.async.wait_group 0;" ::: "memory")

// packed offsets (64-k chunk granularity), element (m|n, k), reduction Ktot
__device__ __forceinline__ size_t apack16(int m, int k, int Ktot) {
    return ((size_t)(m >> 7) * (Ktot >> 6) + (k >> 6)) * 8192
         + (size_t)(((((m >> 4) & 7) << 2) + ((k >> 4) & 3)) * 256
         + (((m & 7) << 2) + ((k & 7) >> 1)) * 8
         + (((k >> 3) & 1) << 2) + (((m >> 3) & 1) << 1) + (k & 1));
}
__device__ __forceinline__ size_t bpack16(int n, int k, int Ktot) {
    return ((size_t)(n >> 7) * (Ktot >> 6) + (k >> 6)) * 8192
         + (size_t)(((((n >> 3) & 15) << 2) + ((k >> 4) & 3)) * 128
         + (((n & 7) << 2) + ((k & 7) >> 1)) * 4
         + (((k >> 3) & 1) << 1) + (k & 1));
}

// ---------------------------------------------------------------------------
// Stage 1: T = class @ M, hi/lo split (3 MMA/k16). 32-k sub-chunks (32KB),
// 3 stages (96KB) + 2 CTAs/SM. Operand loads staged to keep regs <= 128.
// ---------------------------------------------------------------------------
#define G1_SF 16384   // halves per stage (32KB)

__global__ void __launch_bounds__(256, 2)
gemm_split_f16(const __half* __restrict__ Ah, const __half* __restrict__ Al,
               const __half* __restrict__ Bh, const __half* __restrict__ Bl,
               __half* __restrict__ outh)
{
    extern __shared__ char smc[];
    __half* sm = (__half*)smc;

    const int tid = threadIdx.x;
    const int lane = tid & 31;
    const int wid = tid >> 5;
    const int wm = wid >> 2;   // 0..1
    const int wn = wid & 3;    // 0..3
    const int m0 = blockIdx.y * 128;
    const int n0 = blockIdx.x * 128;
    const int NCH = 16;        // 512 k / 32

    const size_t aBlk = (size_t)(m0 >> 7) * 8 * 8192;
    const size_t bBlk = (size_t)(n0 >> 7) * 8 * 8192;

    float macc[4][4][4];
#pragma unroll
    for (int mi = 0; mi < 4; mi++)
#pragma unroll
        for (int ni = 0; ni < 4; ni++)
#pragma unroll
            for (int r = 0; r < 4; r++) macc[mi][ni][r] = 0.0f;

    auto issue = [&](int it, int s) {
        const int c64 = it >> 1, p = it & 1;
        const size_t b64 = (size_t)c64 * 8192;
        const uint32_t smb = smem_u32(sm + s * G1_SF);
        {
            const int q = tid >> 6;
            const int r = (tid & 63) * 8;
            const size_t s0 = aBlk + b64 + (size_t)q * 1024 + p * 512 + r;
            const uint32_t d0 = smb + tid * 16;
            CPA(d0,                Ah + s0);
            CPA(d0 + 4096,         Ah + s0 + 4096);
            CPA(d0 + 8192,         Al + s0);
            CPA(d0 + 8192 + 4096,  Al + s0 + 4096);
        }
        {
            const int run = tid >> 5;
            const int r = (tid & 31) * 8;
            const size_t s0 = bBlk + b64 + (size_t)run * 512 + p * 256 + r;
            const uint32_t d0 = smb + 16384 + tid * 16;
            CPA(d0,                Bh + s0);
            CPA(d0 + 4096,         Bh + s0 + 4096);
            CPA(d0 + 8192,         Bl + s0);
            CPA(d0 + 8192 + 4096,  Bl + s0 + 4096);
        }
        CPA_COMMIT();
    };

    issue(0, 0);
    issue(1, 1);

    int s = 0;
#pragma unroll 1
    for (int it = 0; it < NCH; it++) {
        if (it < NCH - 1) CPA_WAIT1(); else CPA_WAIT0();
        __syncthreads();
        if (it + 2 < NCH) {
            int s2 = s + 2; if (s2 >= 3) s2 -= 3;
            issue(it + 2, s2);
        }

        const __half* pa  = sm + s * G1_SF;
        const __half* pal = pa + 4096;
        const __half* pbh = pa + 8192;
        const __half* pbl = pa + 12288;
#pragma unroll
        for (int kf = 0; kf < 2; kf++) {
            // staged operand loads to cap register pressure at 2 CTAs/SM
            uint4 ah[4];
            uint2 bh[4];
#pragma unroll
            for (int mi = 0; mi < 4; mi++)
                ah[mi] = *(const uint4*)(pa + (wm * 4 + mi) * 512 + kf * 256 + lane * 8);
#pragma unroll
            for (int ni = 0; ni < 4; ni++)
                bh[ni] = *(const uint2*)(pbh + (wn * 4 + ni) * 256 + kf * 128 + lane * 4);
#pragma unroll
            for (int mi = 0; mi < 4; mi++)
#pragma unroll
                for (int ni = 0; ni < 4; ni++)
                    mma_f16(macc[mi][ni], (const uint32_t*)&ah[mi], (const uint32_t*)&bh[ni]);
            {
                uint4 al[4];
#pragma unroll
                for (int mi = 0; mi < 4; mi++)
                    al[mi] = *(const uint4*)(pal + (wm * 4 + mi) * 512 + kf * 256 + lane * 8);
#pragma unroll
                for (int mi = 0; mi < 4; mi++)
#pragma unroll
                    for (int ni = 0; ni < 4; ni++)
                        mma_f16(macc[mi][ni], (const uint32_t*)&al[mi], (const uint32_t*)&bh[ni]);
            }
            {
                uint2 bl[4];
#pragma unroll
                for (int ni = 0; ni < 4; ni++)
                    bl[ni] = *(const uint2*)(pbl + (wn * 4 + ni) * 256 + kf * 128 + lane * 4);
#pragma unroll
                for (int mi = 0; mi < 4; mi++)
#pragma unroll
                    for (int ni = 0; ni < 4; ni++)
                        mma_f16(macc[mi][ni], (const uint32_t*)&ah[mi], (const uint32_t*)&bl[ni]);
            }
        }
        if (++s >= 3) s -= 3;
    }

    // epilogue: A x2^8 * B x2^10 -> T x2^8 => *2^-10
    const int lq = lane >> 2;
    const int ld = lane & 3;
    const float ds = 0.0009765625f;
#pragma unroll
    for (int mi = 0; mi < 4; mi++) {
        const int r = m0 + wm * 64 + mi * 16 + lq;
#pragma unroll
        for (int ni = 0; ni < 4; ni++) {
            const int c = n0 + wn * 32 + ni * 8 + 2 * ld;
#pragma unroll
            for (int rr = 0; rr < 4; rr++) {
                int row = r + (rr >> 1) * 8;
                int col = c + (rr & 1);
                int kp = col & 7, dd = col >> 3;
                outh[(size_t)kp * 2097152 + bpack16(row, dd, 512)] =
                    __float2half_rn(macc[mi][ni][rr] * ds);
            }
        }
    }
}

// ---------------------------------------------------------------------------
// Stage 4: qfp[z] = sc @ class^T (single fp16, 1 MMA/k16). 64-k chunks (32KB),
// 3 stages (96KB) + 2 CTAs/SM, split-K via blockIdx.z.
// ---------------------------------------------------------------------------
#define G4_SF 16384

__global__ void __launch_bounds__(256, 2)
gemm_single_f16(const __half* __restrict__ Ah, const __half* __restrict__ Bh,
                float* __restrict__ out, int Ktot, int kseg)
{
    extern __shared__ char smc[];
    __half* sm = (__half*)smc;

    const int tid = threadIdx.x;
    const int lane = tid & 31;
    const int wid = tid >> 5;
    const int wm = wid >> 2;
    const int wn = wid & 3;
    const int m0 = blockIdx.y * 128;
    const int n0 = blockIdx.x * 128;
    const int kstart = blockIdx.z * kseg;
    const int NCH = kseg / 64;

    const size_t aBlk = ((size_t)(m0 >> 7) * (Ktot >> 6) + (kstart >> 6)) * 8192;
    const size_t bBlk = ((size_t)(n0 >> 7) * (Ktot >> 6) + (kstart >> 6)) * 8192;

    float macc[4][4][4];
#pragma unroll
    for (int mi = 0; mi < 4; mi++)
#pragma unroll
        for (int ni = 0; ni < 4; ni++)
#pragma unroll
            for (int r = 0; r < 4; r++) macc[mi][ni][r] = 0.0f;

    auto issue = [&](int it, int s) {
        const size_t cofs = (size_t)it * 8192 + tid * 8;
        const uint32_t da = smem_u32(sm + s * G4_SF) + tid * 16;
#pragma unroll
        for (int p = 0; p < 4; p++) {
            CPA(da + p * 4096,         Ah + aBlk + cofs + p * 2048);
            CPA(da + 16384 + p * 4096, Bh + bBlk + cofs + p * 2048);
        }
        CPA_COMMIT();
    };

    issue(0, 0);
    issue(1, 1);

    int s = 0;
#pragma unroll 1
    for (int it = 0; it < NCH; it++) {
        if (it < NCH - 1) CPA_WAIT1(); else CPA_WAIT0();
        __syncthreads();
        if (it + 2 < NCH) {
            int s2 = s + 2; if (s2 >= 3) s2 -= 3;
            issue(it + 2, s2);
        }

        const __half* pa = sm + s * G4_SF;
        const __half* pb = pa + 8192;
#pragma unroll
        for (int kk = 0; kk < 4; kk++) {
            uint4 a[4];
            uint2 b[4];
#pragma unroll
            for (int mi = 0; mi < 4; mi++)
                a[mi] = *(const uint4*)(pa + (((wm * 4 + mi) * 4 + kk) << 8) + lane * 8);
#pragma unroll
            for (int ni = 0; ni < 4; ni++)
                b[ni] = *(const uint2*)(pb + (((wn * 4 + ni) * 4 + kk) << 7) + lane * 4);
#pragma unroll
            for (int mi = 0; mi < 4; mi++)
#pragma unroll
                for (int ni = 0; ni < 4; ni++)
                    mma_f16(macc[mi][ni], (const uint32_t*)&a[mi], (const uint32_t*)&b[ni]);
        }
        if (++s >= 3) s -= 3;
    }

    // sc x2^6 * class x2^8 -> *2^-14
    const int lq = lane >> 2;
    const int ld = lane & 3;
    const float ds = 6.103515625e-05f;
    float* ob = out + (size_t)blockIdx.z * 4096 * 512;
#pragma unroll
    for (int mi = 0; mi < 4; mi++) {
        const int r = m0 + wm * 64 + mi * 16 + lq;
#pragma unroll
        for (int ni = 0; ni < 4; ni++) {
            const int c = n0 + wn * 32 + ni * 8 + 2 * ld;
            *(float2*)(ob + (size_t)r * 512 + c) =
                make_float2(macc[mi][ni][0] * ds, macc[mi][ni][1] * ds);
            *(float2*)(ob + (size_t)(r + 8) * 512 + c) =
                make_float2(macc[mi][ni][2] * ds, macc[mi][ni][3] * ds);
        }
    }
}

// ---------------------------------------------------------------------------
// Stage 2: fused bilinear + relu + score (exact R11 shape: 128-d chunks,
// 3x64KB stages, 1 CTA/SM; 8-cp.async issue loop).
// ---------------------------------------------------------------------------
#define S2_SF 32768                       // halves per stage (A 16K + B 16K)
#define S2_SMEM (3 * S2_SF * 2)           // 196608 B

__global__ void __launch_bounds__(256, 1)
stage2_f16(const __half* __restrict__ q16, const __half* __restrict__ T16,
           const float* __restrict__ score_w, const float* __restrict__ score_b,
           float* __restrict__ other)
{
    extern __shared__ char smc[];
    __half* sm = (__half*)smc;
    const int tid = threadIdx.x;
    const int lane = tid & 31;
    const int wid = tid >> 5;
    const int wm = wid >> 2;
    const int wn = wid & 3;
    const int q0 = blockIdx.y * 128;
    const int c0 = blockIdx.x * 128;

    const size_t aBase = (size_t)(q0 >> 7) * 8 * 8192;
    const size_t bBase = (size_t)(c0 >> 7) * 8 * 8192;

    float sacc[4][4][4];
#pragma unroll
    for (int mi = 0; mi < 4; mi++)
#pragma unroll
        for (int ni = 0; ni < 4; ni++)
#pragma unroll
            for (int r = 0; r < 4; r++) sacc[mi][ni][r] = 0.0f;

    // it = k*4 + t (t: 128-d chunk within slab); 8x16B per thread per operand
    auto issue = [&](int it, int s) {
        const int k = it >> 2, t = it & 3;
        const __half* srcA = q16 + aBase + (size_t)t * 16384 + tid * 8;
        const __half* srcB = T16 + (size_t)k * 2097152 + bBase + (size_t)t * 16384 + tid * 8;
        uint32_t da = smem_u32(sm + s * S2_SF) + tid * 16;
        uint32_t db = da + 32768;
#pragma unroll
        for (int i = 0; i < 8; i++) {
            CPA(da + i * 4096, srcA + i * 2048);
            CPA(db + i * 4096, srcB + i * 2048);
        }
        CPA_COMMIT();
    };

    issue(0, 0);
    issue(1, 1);

    float macc[4][4][4];
    int s = 0;
#pragma unroll 1
    for (int it = 0; it < 32; it++) {
        const int k = it >> 2, t = it & 3;
        if (t == 0) {
#pragma unroll
            for (int mi = 0; mi < 4; mi++)
#pragma unroll
                for (int ni = 0; ni < 4; ni++)
#pragma unroll
                    for (int r = 0; r < 4; r++) macc[mi][ni][r] = 0.0f;
        }

        if (it < 31) CPA_WAIT1(); else CPA_WAIT0();
        __syncthreads();
        if (it + 2 < 32) {
            int s2 = s + 2; if (s2 >= 3) s2 -= 3;
            issue(it + 2, s2);
        }

        const __half* pa = sm + s * S2_SF;
        const __half* pb = pa + 16384;
#pragma unroll
        for (int kk = 0; kk < 8; kk++) {
            const int sub = (kk >> 2) * 8192;
            const int kf = kk & 3;
            uint4 a[4];
            uint2 b[4];
#pragma unroll
            for (int mi = 0; mi < 4; mi++)
                a[mi] = *(const uint4*)(pa + sub + (((wm * 4 + mi) * 4 + kf) << 8) + lane * 8);
#pragma unroll
            for (int ni = 0; ni < 4; ni++)
                b[ni] = *(const uint2*)(pb + sub + (((wn * 4 + ni) * 4 + kf) << 7) + lane * 4);
#pragma unroll
            for (int mi = 0; mi < 4; mi++)
#pragma unroll
                for (int ni = 0; ni < 4; ni++)
                    mma_f16(macc[mi][ni], (const uint32_t*)&a[mi], (const uint32_t*)&b[ni]);
        }

        if (t == 3) {
            // acc = P * 2^16 (q x2^8, T x2^8): fold 2^-16 into w
            const float w = __ldg(score_w + k) * 1.52587890625e-05f;
#pragma unroll
            for (int mi = 0; mi < 4; mi++)
#pragma unroll
                for (int ni = 0; ni < 4; ni++)
#pragma unroll
                    for (int r = 0; r < 4; r++)
                        sacc[mi][ni][r] = fmaf(fmaxf(macc[mi][ni][r], 0.0f), w,
                                               sacc[mi][ni][r]);
        }
        if (++s >= 3) s -= 3;
    }

    const int lq = lane >> 2;
    const int ld = lane & 3;
    const float sb = __ldg(score_b);
#pragma unroll
    for (int mi = 0; mi < 4; mi++) {
        const int q = q0 + wm * 64 + mi * 16 + lq;
#pragma unroll
        for (int ni = 0; ni < 4; ni++) {
            const int c = c0 + wn * 32 + ni * 8 + 2 * ld;
            *(float2*)(other + (size_t)q * 4096 + c) =
                make_float2(sb + sacc[mi][ni][0], sb + sacc[mi][ni][1]);
            *(float2*)(other + (size_t)(q + 8) * 4096 + c) =
                make_float2(sb + sacc[mi][ni][2], sb + sacc[mi][ni][3]);
        }
    }
}

// ---------------------------------------------------------------------------
// Softmax (paired rows q, q+8); fp16 A-pack output (Ktot=4096, x2^6).
// ---------------------------------------------------------------------------
__global__ void softmax_pack2(const float* __restrict__ o, __half* __restrict__ sc)
{
    const int b = blockIdx.x;
    const int qa = ((b >> 3) << 4) | (b & 7);
    const int tid = threadIdx.x;

    float v0[16], v1[16];
    {
        const float4* p0 = (const float4*)(o + (size_t)qa * 4096) + tid * 4;
        const float4* p1 = (const float4*)(o + (size_t)(qa + 8) * 4096) + tid * 4;
#pragma unroll
        for (int i = 0; i < 4; i++) {
            float4 x = p0[i];
            v0[i * 4] = x.x; v0[i * 4 + 1] = x.y; v0[i * 4 + 2] = x.z; v0[i * 4 + 3] = x.w;
            float4 y = p1[i];
            v1[i * 4] = y.x; v1[i * 4 + 1] = y.y; v1[i * 4 + 2] = y.z; v1[i * 4 + 3] = y.w;
        }
    }
    float mx0 = -1e30f, mx1 = -1e30f;
#pragma unroll
    for (int i = 0; i < 16; i++) { mx0 = fmaxf(mx0, v0[i]); mx1 = fmaxf(mx1, v1[i]); }

    __shared__ float sm0[8], sm1[8];
#pragma unroll
    for (int o2 = 16; o2 > 0; o2 >>= 1) {
        mx0 = fmaxf(mx0, __shfl_xor_sync(0xffffffffu, mx0, o2));
        mx1 = fmaxf(mx1, __shfl_xor_sync(0xffffffffu, mx1, o2));
    }
    if ((tid & 31) == 0) { sm0[tid >> 5] = mx0; sm1[tid >> 5] = mx1; }
    __syncthreads();
    mx0 = sm0[0]; mx1 = sm1[0];
#pragma unroll
    for (int i = 1; i < 8; i++) { mx0 = fmaxf(mx0, sm0[i]); mx1 = fmaxf(mx1, sm1[i]); }
    __syncthreads();

    float s0 = 0.0f, s1 = 0.0f;
#pragma unroll
    for (int i = 0; i < 16; i++) {
        v0[i] = expf(v0[i] - mx0); s0 += v0[i];
        v1[i] = expf(v1[i] - mx1); s1 += v1[i];
    }
#pragma unroll
    for (int o2 = 16; o2 > 0; o2 >>= 1) {
        s0 += __shfl_xor_sync(0xffffffffu, s0, o2);
        s1 += __shfl_xor_sync(0xffffffffu, s1, o2);
    }
    if ((tid & 31) == 0) { sm0[tid >> 5] = s0; sm1[tid >> 5] = s1; }
    __syncthreads();
    s0 = 0.0f; s1 = 0.0f;
#pragma unroll
    for (int i = 0; i < 8; i++) { s0 += sm0[i]; s1 += sm1[i]; }
    const float i0 = 64.0f / s0, i1 = 64.0f / s1;   // fold x2^6 scale

    __half hbuf[32];
#pragma unroll
    for (int j = 0; j < 32; j++) {
        int t2 = j >> 3, kb3 = (j >> 2) & 1, mrow = (j >> 1) & 1, h = j & 1;
        int kl = kb3 * 8 + t2 * 2 + h;
        hbuf[j] = __float2half_rn(mrow ? v1[kl] * i1 : v0[kl] * i0);
    }
    __half* dst = sc + apack16(qa, tid * 16, 4096);
#pragma unroll
    for (int j = 0; j < 4; j++)
        *(uint4*)(dst + j * 8) = *(const uint4*)(hbuf + j * 8);
}

// ---------------------------------------------------------------------------
// Fused stage 5: qf = query + sum_z qfp[z] (smem), out = tanh(qf @ hwT + b).
// ---------------------------------------------------------------------------
__global__ void __launch_bounds__(256, 2)
stage5_fused(const float* __restrict__ query, const float* __restrict__ qfp,
             const float* __restrict__ hwT, const float* __restrict__ hash_b,
             float* __restrict__ out)
{
    __shared__ float qf_s[16 * 512];
    const int tid = threadIdx.x;
    const int qbase = blockIdx.x * 16;
    const size_t S = (size_t)4096 * 512;
    const size_t gbase = (size_t)qbase * 512;

#pragma unroll
    for (int j = 0; j < 8; j++) {
        int i4 = tid + j * 256;
        size_t g = gbase + (size_t)i4 * 4;
        float4 acc = *(const float4*)(query + g);
#pragma unroll
        for (int z = 0; z < 8; z++) {
            float4 p = *(const float4*)(qfp + z * S + g);
            acc.x += p.x; acc.y += p.y; acc.z += p.z; acc.w += p.w;
        }
        *(float4*)(qf_s + i4 * 4) = acc;
    }
    __syncthreads();

    const int q = tid >> 4;
    const int lb = (tid & 15) * 4;
    float a0 = 0, a1 = 0, a2 = 0, a3 = 0;
    const float* qr = qf_s + q * 512;
#pragma unroll 4
    for (int d = 0; d < 512; d += 4) {
        float4 qv = *(const float4*)(qr + d);
        float4 h0 = __ldg((const float4*)(hwT + (size_t)d * 64 + lb));
        float4 h1 = __ldg((const float4*)(hwT + (size_t)(d + 1) * 64 + lb));
        float4 h2 = __ldg((const float4*)(hwT + (size_t)(d + 2) * 64 + lb));
        float4 h3 = __ldg((const float4*)(hwT + (size_t)(d + 3) * 64 + lb));
        a0 = fmaf(qv.x, h0.x, fmaf(qv.y, h1.x, fmaf(qv.z, h2.x, fmaf(qv.w, h3.x, a0))));
        a1 = fmaf(qv.x, h0.y, fmaf(qv.y, h1.y, fmaf(qv.z, h2.y, fmaf(qv.w, h3.y, a1))));
        a2 = fmaf(qv.x, h0.z, fmaf(qv.y, h1.z, fmaf(qv.z, h2.z, fmaf(qv.w, h3.z, a2))));
        a3 = fmaf(qv.x, h0.w, fmaf(qv.y, h1.w, fmaf(qv.z, h2.w, fmaf(qv.w, h3.w, a3))));
    }
    float4 hb = __ldg((const float4*)(hash_b + lb));
    float4 r = make_float4(tanhf(a0 + hb.x), tanhf(a1 + hb.y),
                           tanhf(a2 + hb.z), tanhf(a3 + hb.w));
    *(float4*)(out + (size_t)(qbase + q) * 64 + lb) = r;
}

// ---------------------------------------------------------------------------
// Prep kernels
// ---------------------------------------------------------------------------
__global__ void transpose_hw(const float* __restrict__ hw)
{
    int idx = blockIdx.x * blockDim.x + threadIdx.x;
    int l = idx >> 9;
    int d = idx & 511;
    g_hwT[d * 64 + l] = hw[idx];
}

// query -> A-pack fp16 x2^8. Thread handles rows (m, m+8) x 16 k -> 64B store.
__global__ void pack_q16(const float* __restrict__ q)
{
    int t = blockIdx.x * blockDim.x + threadIdx.x;
    int kg = t & 31;
    int pr = t >> 5;
    int m0 = ((pr >> 3) << 4) | (pr & 7);
    int kb = kg * 16;

    float v0[16], v1[16];
    const float4* p0 = (const float4*)(q + (size_t)m0 * 512 + kb);
    const float4* p1 = (const float4*)(q + (size_t)(m0 + 8) * 512 + kb);
#pragma unroll
    for (int i = 0; i < 4; i++) {
        float4 x = p0[i];
        v0[i*4] = x.x; v0[i*4+1] = x.y; v0[i*4+2] = x.z; v0[i*4+3] = x.w;
        float4 y = p1[i];
        v1[i*4] = y.x; v1[i*4+1] = y.y; v1[i*4+2] = y.z; v1[i*4+3] = y.w;
    }
    __half hbuf[32];
#pragma unroll
    for (int j = 0; j < 32; j++) {
        int t2 = j >> 3, kb3 = (j >> 2) & 1, mrow = (j >> 1) & 1, h = j & 1;
        int kl = kb3 * 8 + t2 * 2 + h;
        hbuf[j] = __float2half_rn((mrow ? v1[kl] : v0[kl]) * 256.0f);
    }
    __half* dst = g_q16 + apack16(m0, kb, 512);
#pragma unroll
    for (int j = 0; j < 4; j++)
        *(uint4*)(dst + j * 8) = *(const uint4*)(hbuf + j * 8);
}

// class -> A-pack fp16 hi/lo x2^8
__global__ void pack_classA16(const float* __restrict__ cv)
{
    int t = blockIdx.x * blockDim.x + threadIdx.x;
    int kg = t & 31;
    int pr = t >> 5;
    int m0 = ((pr >> 3) << 4) | (pr & 7);
    int kb = kg * 16;

    float v0[16], v1[16];
    const float4* p0 = (const float4*)(cv + (size_t)m0 * 512 + kb);
    const float4* p1 = (const float4*)(cv + (size_t)(m0 + 8) * 512 + kb);
#pragma unroll
    for (int i = 0; i < 4; i++) {
        float4 x = p0[i];
        v0[i*4] = x.x; v0[i*4+1] = x.y; v0[i*4+2] = x.z; v0[i*4+3] = x.w;
        float4 y = p1[i];
        v1[i*4] = y.x; v1[i*4+1] = y.y; v1[i*4+2] = y.z; v1[i*4+3] = y.w;
    }
    __half hb[32], lb[32];
#pragma unroll
    for (int j = 0; j < 32; j++) {
        int t2 = j >> 3, kb3 = (j >> 2) & 1, mrow = (j >> 1) & 1, h = j & 1;
        int kl = kb3 * 8 + t2 * 2 + h;
        float v = (mrow ? v1[kl] : v0[kl]) * 256.0f;
        __half hi = __float2half_rn(v);
        hb[j] = hi;
        lb[j] = __float2half_rn(v - __half2float(hi));
    }
    size_t off = apack16(m0, kb, 512);
#pragma unroll
    for (int j = 0; j < 4; j++) {
        *(uint4*)(g_cah + off + j * 8) = *(const uint4*)(hb + j * 8);
        *(uint4*)(g_cal + off + j * 8) = *(const uint4*)(lb + j * 8);
    }
}

// in [R][C] (R=k-dim, C=n-dim) -> B-pack fp16 hi/lo, one thread per 16-k group.
__global__ void pack_B16_split(const float* __restrict__ in,
                               __half* __restrict__ ohi, __half* __restrict__ olo,
                               int R, int C, float scale)
{
    unsigned tt = blockIdx.x * blockDim.x + threadIdx.x;
    unsigned k16 = tt / (unsigned)C;
    unsigned n = tt - k16 * (unsigned)C;
    int kb = (int)k16 * 16;

    unsigned short h[16], l[16];
#pragma unroll
    for (int i = 0; i < 16; i++) {
        float v = in[(size_t)(kb + i) * C + n] * scale;
        __half hv = __float2half_rn(v);
        h[i] = __half_as_ushort(hv);
        l[i] = __half_as_ushort(__float2half_rn(v - __half2float(hv)));
    }
    size_t base = bpack16((int)n, kb, R);
    const int map[16] = {0,1,8,9,2,3,10,11,4,5,12,13,6,7,14,15};
    uint32_t uh[8], ul[8];
#pragma unroll
    for (int j = 0; j < 8; j++) {
        uh[j] = (uint32_t)h[map[2*j]] | ((uint32_t)h[map[2*j+1]] << 16);
        ul[j] = (uint32_t)l[map[2*j]] | ((uint32_t)l[map[2*j+1]] << 16);
    }
    *(uint4*)(ohi + base)     = make_uint4(uh[0], uh[1], uh[2], uh[3]);
    *(uint4*)(ohi + base + 8) = make_uint4(uh[4], uh[5], uh[6], uh[7]);
    *(uint4*)(olo + base)     = make_uint4(ul[0], ul[1], ul[2], ul[3]);
    *(uint4*)(olo + base + 8) = make_uint4(ul[4], ul[5], ul[6], ul[7]);
}

// class^T -> B-pack fp16 single x2^8 (N=512 d-dim, K=4096 c-dim)
__global__ void pack_classB16(const float* __restrict__ cv)
{
    unsigned tt = blockIdx.x * blockDim.x + threadIdx.x;
    unsigned c16 = tt / 512u;
    unsigned d = tt - c16 * 512u;
    int cb = (int)c16 * 16;

    unsigned short h[16];
#pragma unroll
    for (int i = 0; i < 16; i++)
        h[i] = __half_as_ushort(__float2half_rn(cv[(size_t)(cb + i) * 512 + d] * 256.0f));
    size_t base = bpack16((int)d, cb, 4096);
    const int map[16] = {0,1,8,9,2,3,10,11,4,5,12,13,6,7,14,15};
    uint32_t u[8];
#pragma unroll
    for (int j = 0; j < 8; j++)
        u[j] = (uint32_t)h[map[2*j]] | ((uint32_t)h[map[2*j+1]] << 16);
    *(uint4*)(g_cbh + base)     = make_uint4(u[0], u[1], u[2], u[3]);
    *(uint4*)(g_cbh + base + 8) = make_uint4(u[4], u[5], u[6], u[7]);
}

// ---------------------------------------------------------------------------
extern "C" void kernel_launch(void* const* d_in, const int* in_sizes, int n_in,
                              void* d_out, int out_size)
{
    const float* class_v = (const float*)d_in[0];
    const float* query_v = (const float*)d_in[1];
    const float* Mmat    = (const float*)d_in[2];
    const float* score_w = (const float*)d_in[3];
    const float* score_b = (const float*)d_in[4];
    const float* hash_w  = (const float*)d_in[5];
    const float* hash_b  = (const float*)d_in[6];
    float* out = (float*)d_out;

    float *other, *qfp, *hwT;
    __half *T16, *sc16, *q16, *cah, *cal, *mbh, *mbl, *cbh;
    cudaGetSymbolAddress((void**)&T16, g_T16);
    cudaGetSymbolAddress((void**)&other, g_other);
    cudaGetSymbolAddress((void**)&sc16, g_sc16);
    cudaGetSymbolAddress((void**)&q16, g_q16);
    cudaGetSymbolAddress((void**)&cah, g_cah);
    cudaGetSymbolAddress((void**)&cal, g_cal);
    cudaGetSymbolAddress((void**)&mbh, g_mbh);
    cudaGetSymbolAddress((void**)&mbl, g_mbl);
    cudaGetSymbolAddress((void**)&cbh, g_cbh);
    cudaGetSymbolAddress((void**)&qfp, g_qfp);
    cudaGetSymbolAddress((void**)&hwT, g_hwT);

    const int SM96  = 3 * 32768;   // 98304 B  (2 CTAs/SM)
    cudaFuncSetAttribute(gemm_split_f16, cudaFuncAttributeMaxDynamicSharedMemorySize, SM96);
    cudaFuncSetAttribute(gemm_single_f16, cudaFuncAttributeMaxDynamicSharedMemorySize, SM96);
    cudaFuncSetAttribute(stage2_f16, cudaFuncAttributeMaxDynamicSharedMemorySize, S2_SMEM);

    // prep
    pack_q16<<<256, 256>>>(query_v);
    pack_classA16<<<256, 256>>>(class_v);
    pack_B16_split<<<512, 256>>>(Mmat, mbh, mbl, 512, 4096, 1024.0f);  // M x2^10

    // Stage 1: T = class @ M  (fp16 3-MMA split, 2 CTAs/SM)
    gemm_split_f16<<<dim3(32, 32), 256, SM96>>>(cah, cal, mbh, mbl, T16);

    pack_classB16<<<512, 256>>>(class_v);

    // Stage 2: fused bilinear + relu + score (R11 shape)
    stage2_f16<<<dim3(32, 32), 256, S2_SMEM>>>(q16, T16, score_w, score_b, other);

    // Stage 3: softmax -> fp16 packed scores
    softmax_pack2<<<2048, 256>>>(other, sc16);

    // Stage 4: qf partials = sc @ class (fp16 single, split-K=8, 2 CTAs/SM)
    gemm_single_f16<<<dim3(4, 32, 8), 256, SM96>>>(sc16, cbh, qfp, 4096, 512);

    transpose_hw<<<128, 256>>>(hash_w);

    // Stage 5 (fused reduce + residual + tanh GEMM)
    stage5_fused<<<256, 256>>>(query_v, qfp, hwT, hash_b, out);
}

// round 17
// speedup vs baseline: 1.2271x; 1.1306x over previous
#include <cuda_runtime.h>
#include <cuda_fp16.h>
#include <math.h>
#include <stdint.h>

// ---------------------------------------------------------------------------
// Dims: D=512, K=8, L=64, Q=4096, C=4096.  All GEMMs on fp16 m16n8k16 mma.
//   T (B-pack fp16, x2^8)  = class @ M        (3-MMA hi/lo split, ~2^-22)
//   other[q,c] = b + sum_k w_k*relu(q.Tk)     (1 MMA/k16)
//   sc  = softmax_rows(other)                 (A-pack fp16, x2^6)
//   qfp[z] = sc @ class                       (1 MMA/k16, split-K=8)
//   out = tanh((query + sum_z qfp) @ hash_w^T + b)   (fused SIMT)
// Target sm_103 (no 'a'): mma.sync/cp.async only.
// stage1/stage4: 96KB smem + launch_bounds(256,2) -> 2 CTAs/SM.
// stage1 epilogue: smem-staged -> fully coalesced uint4 stores.
// stage2: R11 shape (1 CTA, 192KB); launch #4 for ncu capture.
// ---------------------------------------------------------------------------

__device__ __half g_T16[(size_t)8 * 4096 * 512];   // T, B-pack, x2^8 (32MB)
__device__ float  g_other[(size_t)4096 * 4096];    // logits fp32 (64MB)
__device__ __half g_sc16[(size_t)4096 * 4096];     // scores A-pack x2^6 (32MB)
__device__ __half g_q16[(size_t)4096 * 512];       // query A-pack x2^8
__device__ __half g_cah[(size_t)4096 * 512];       // class A-pack hi (x2^8)
__device__ __half g_cal[(size_t)4096 * 512];       // class A-pack lo
__device__ __half g_mbh[(size_t)4096 * 512];       // M^T B-pack hi (x2^10)
__device__ __half g_mbl[(size_t)4096 * 512];       // M^T B-pack lo
__device__ __half g_cbh[(size_t)512 * 4096];       // class^T B-pack (x2^8)
__device__ float  g_qfp[(size_t)8 * 4096 * 512];   // split-K partials (64MB)
__device__ float  g_hwT[512 * 64];

// ------------------------------ helpers -----------------------------------
__device__ __forceinline__ uint32_t smem_u32(const void* p) {
    uint32_t a;
    asm("{ .reg .u64 t; cvta.to.shared.u64 t, %1; cvt.u32.u64 %0, t; }" : "=r"(a) : "l"(p));
    return a;
}
__device__ __forceinline__ void mma_f16(float* c, const uint32_t* a, const uint32_t* b) {
    asm volatile(
        "mma.sync.aligned.m16n8k16.row.col.f32.f16.f16.f32 "
        "{%0,%1,%2,%3}, {%4,%5,%6,%7}, {%8,%9}, {%0,%1,%2,%3};"
        : "+f"(c[0]), "+f"(c[1]), "+f"(c[2]), "+f"(c[3])
        : "r"(a[0]), "r"(a[1]), "r"(a[2]), "r"(a[3]), "r"(b[0]), "r"(b[1]));
}
#define CPA(dst, src) \
    asm volatile("cp.async.cg.shared.global [%0], [%1], 16;" :: "r"(dst), "l"(src))
#define CPA_COMMIT() asm volatile("cp.async.commit_group;" ::: "memory")
#define CPA_WAIT1()  asm volatile("cp.async.wait_group 1;" ::: "memory")
#define CPA_WAIT0()  asm volatile("cp.async.wait_group 0;" ::: "memory")

// packed offsets (64-k chunk granularity), element (m|n, k), reduction Ktot
__device__ __forceinline__ size_t apack16(int m, int k, int Ktot) {
    return ((size_t)(m >> 7) * (Ktot >> 6) + (k >> 6)) * 8192
         + (size_t)(((((m >> 4) & 7) << 2) + ((k >> 4) & 3)) * 256
         + (((m & 7) << 2) + ((k & 7) >> 1)) * 8
         + (((k >> 3) & 1) << 2) + (((m >> 3) & 1) << 1) + (k & 1));
}
__device__ __forceinline__ size_t bpack16(int n, int k, int Ktot) {
    return ((size_t)(n >> 7) * (Ktot >> 6) + (k >> 6)) * 8192
         + (size_t)(((((n >> 3) & 15) << 2) + ((k >> 4) & 3)) * 128
         + (((n & 7) << 2) + ((k & 7) >> 1)) * 4
         + (((k >> 3) & 1) << 1) + (k & 1));
}

// ---------------------------------------------------------------------------
// Stage 1: T = class @ M, hi/lo split both sides (3 MMA/k16). 32-k sub-chunks
// (32KB), 3 stages (96KB), 2 CTAs/SM. Staged (coalesced) epilogue.
// ---------------------------------------------------------------------------
#define G1_SF 16384   // halves per stage (32KB)

__global__ void __launch_bounds__(256, 2)
gemm_split_f16(const __half* __restrict__ Ah, const __half* __restrict__ Al,
               const __half* __restrict__ Bh, const __half* __restrict__ Bl,
               __half* __restrict__ outh)
{
    extern __shared__ char smc[];
    __half* sm = (__half*)smc;

    const int tid = threadIdx.x;
    const int lane = tid & 31;
    const int wid = tid >> 5;
    const int wm = wid >> 2;   // 0..1
    const int wn = wid & 3;    // 0..3
    const int m0 = blockIdx.y * 128;
    const int n0 = blockIdx.x * 128;
    const int NCH = 16;        // 512 k / 32

    const size_t aBlk = (size_t)(m0 >> 7) * 8 * 8192;
    const size_t bBlk = (size_t)(n0 >> 7) * 8 * 8192;

    float macc[4][4][4];
#pragma unroll
    for (int mi = 0; mi < 4; mi++)
#pragma unroll
        for (int ni = 0; ni < 4; ni++)
#pragma unroll
            for (int r = 0; r < 4; r++) macc[mi][ni][r] = 0.0f;

    auto issue = [&](int it, int s) {
        const int c64 = it >> 1, p = it & 1;
        const size_t b64 = (size_t)c64 * 8192;
        const uint32_t smb = smem_u32(sm + s * G1_SF);
        {
            const int q = tid >> 6;
            const int r = (tid & 63) * 8;
            const size_t s0 = aBlk + b64 + (size_t)q * 1024 + p * 512 + r;
            const uint32_t d0 = smb + tid * 16;
            CPA(d0,               Ah + s0);
            CPA(d0 + 4096,        Ah + s0 + 4096);
            CPA(d0 + 8192,        Al + s0);
            CPA(d0 + 8192 + 4096, Al + s0 + 4096);
        }
        {
            const int run = tid >> 5;
            const int r = (tid & 31) * 8;
            const size_t s0 = bBlk + b64 + (size_t)run * 512 + p * 256 + r;
            const uint32_t d0 = smb + 16384 + tid * 16;
            CPA(d0,               Bh + s0);
            CPA(d0 + 4096,        Bh + s0 + 4096);
            CPA(d0 + 8192,        Bl + s0);
            CPA(d0 + 8192 + 4096, Bl + s0 + 4096);
        }
        CPA_COMMIT();
    };

    issue(0, 0);
    issue(1, 1);

    int s = 0;
#pragma unroll 1
    for (int it = 0; it < NCH; it++) {
        if (it < NCH - 1) CPA_WAIT1(); else CPA_WAIT0();
        __syncthreads();
        if (it + 2 < NCH) {
            int s2 = s + 2; if (s2 >= 3) s2 -= 3;
            issue(it + 2, s2);
        }

        const __half* pa  = sm + s * G1_SF;
        const __half* pal = pa + 4096;
        const __half* pbh = pa + 8192;
        const __half* pbl = pa + 12288;
#pragma unroll
        for (int kf = 0; kf < 2; kf++) {
            uint4 ah[4];
            uint2 bh[4];
#pragma unroll
            for (int mi = 0; mi < 4; mi++)
                ah[mi] = *(const uint4*)(pa + (wm * 4 + mi) * 512 + kf * 256 + lane * 8);
#pragma unroll
            for (int ni = 0; ni < 4; ni++)
                bh[ni] = *(const uint2*)(pbh + (wn * 4 + ni) * 256 + kf * 128 + lane * 4);
#pragma unroll
            for (int mi = 0; mi < 4; mi++)
#pragma unroll
                for (int ni = 0; ni < 4; ni++)
                    mma_f16(macc[mi][ni], (const uint32_t*)&ah[mi], (const uint32_t*)&bh[ni]);
            {
                uint4 al[4];
#pragma unroll
                for (int mi = 0; mi < 4; mi++)
                    al[mi] = *(const uint4*)(pal + (wm * 4 + mi) * 512 + kf * 256 + lane * 8);
#pragma unroll
                for (int mi = 0; mi < 4; mi++)
#pragma unroll
                    for (int ni = 0; ni < 4; ni++)
                        mma_f16(macc[mi][ni], (const uint32_t*)&al[mi], (const uint32_t*)&bh[ni]);
            }
            {
                uint2 bl[4];
#pragma unroll
                for (int ni = 0; ni < 4; ni++)
                    bl[ni] = *(const uint2*)(pbl + (wn * 4 + ni) * 256 + kf * 128 + lane * 4);
#pragma unroll
                for (int mi = 0; mi < 4; mi++)
#pragma unroll
                    for (int ni = 0; ni < 4; ni++)
                        mma_f16(macc[mi][ni], (const uint32_t*)&ah[mi], (const uint32_t*)&bl[ni]);
            }
        }
        if (++s >= 3) s -= 3;
    }

    // ---- staged epilogue: pack into smem, then coalesced uint4 stores ----
    // values: T = acc * 2^-10 (A x2^8 * B x2^10 -> x2^18; T stored x2^8)
    __syncthreads();   // all MMA smem reads done before reuse
    __half* st = sm;   // staging: [kp][2056 halves] (2048 used)
    const int lq = lane >> 2;
    const int ld = lane & 3;
    const float ds = 0.0009765625f;
#pragma unroll
    for (int mi = 0; mi < 4; mi++) {
#pragma unroll
        for (int np = 0; np < 2; np++) {
            const int inner0 = (lq * 4 + ((wn * 2 + np) & 3)) * 4
                             + (((2 * wn + np) >> 2) << 1);
#pragma unroll
            for (int rr = 0; rr < 4; rr++) {
                const int kp = 2 * ld + (rr & 1);
                const int rg = wm * 8 + mi * 2 + (rr >> 1);
                __half2 hv = __floats2half2_rn(macc[mi][2 * np][rr] * ds,
                                               macc[mi][2 * np + 1][rr] * ds);
                *(__half2*)(st + kp * 2056 + rg * 128 + inner0) = hv;
            }
        }
    }
    __syncthreads();
    const size_t chunkBase = ((size_t)(m0 >> 7) * 8 + (n0 >> 9)) * 8192;
    const int cdd = (n0 >> 7) & 3;
#pragma unroll
    for (int w = 0; w < 8; w++) {
        int u = tid + w * 256;
        int kp = u >> 8, rem = u & 255;
        int rg = rem >> 4, i8 = (rem & 15) * 8;
        *(uint4*)(outh + (size_t)kp * 2097152 + chunkBase
                  + (size_t)(rg * 4 + cdd) * 128 + i8) =
            *(const uint4*)(st + kp * 2056 + rg * 128 + i8);
    }
}

// ---------------------------------------------------------------------------
// Stage 4: qfp[z] = sc @ class^T (single fp16, 1 MMA/k16). 64-k chunks (32KB),
// 3 stages (96KB) + 2 CTAs/SM, split-K via blockIdx.z.
// ---------------------------------------------------------------------------
#define G4_SF 16384

__global__ void __launch_bounds__(256, 2)
gemm_single_f16(const __half* __restrict__ Ah, const __half* __restrict__ Bh,
                float* __restrict__ out, int Ktot, int kseg)
{
    extern __shared__ char smc[];
    __half* sm = (__half*)smc;

    const int tid = threadIdx.x;
    const int lane = tid & 31;
    const int wid = tid >> 5;
    const int wm = wid >> 2;
    const int wn = wid & 3;
    const int m0 = blockIdx.y * 128;
    const int n0 = blockIdx.x * 128;
    const int kstart = blockIdx.z * kseg;
    const int NCH = kseg / 64;

    const size_t aBlk = ((size_t)(m0 >> 7) * (Ktot >> 6) + (kstart >> 6)) * 8192;
    const size_t bBlk = ((size_t)(n0 >> 7) * (Ktot >> 6) + (kstart >> 6)) * 8192;

    float macc[4][4][4];
#pragma unroll
    for (int mi = 0; mi < 4; mi++)
#pragma unroll
        for (int ni = 0; ni < 4; ni++)
#pragma unroll
            for (int r = 0; r < 4; r++) macc[mi][ni][r] = 0.0f;

    auto issue = [&](int it, int s) {
        const size_t cofs = (size_t)it * 8192 + tid * 8;
        const uint32_t da = smem_u32(sm + s * G4_SF) + tid * 16;
#pragma unroll
        for (int p = 0; p < 4; p++) {
            CPA(da + p * 4096,         Ah + aBlk + cofs + p * 2048);
            CPA(da + 16384 + p * 4096, Bh + bBlk + cofs + p * 2048);
        }
        CPA_COMMIT();
    };

    issue(0, 0);
    issue(1, 1);

    int s = 0;
#pragma unroll 1
    for (int it = 0; it < NCH; it++) {
        if (it < NCH - 1) CPA_WAIT1(); else CPA_WAIT0();
        __syncthreads();
        if (it + 2 < NCH) {
            int s2 = s + 2; if (s2 >= 3) s2 -= 3;
            issue(it + 2, s2);
        }

        const __half* pa = sm + s * G4_SF;
        const __half* pb = pa + 8192;
#pragma unroll
        for (int kk = 0; kk < 4; kk++) {
            uint4 a[4];
            uint2 b[4];
#pragma unroll
            for (int mi = 0; mi < 4; mi++)
                a[mi] = *(const uint4*)(pa + (((wm * 4 + mi) * 4 + kk) << 8) + lane * 8);
#pragma unroll
            for (int ni = 0; ni < 4; ni++)
                b[ni] = *(const uint2*)(pb + (((wn * 4 + ni) * 4 + kk) << 7) + lane * 4);
#pragma unroll
            for (int mi = 0; mi < 4; mi++)
#pragma unroll
                for (int ni = 0; ni < 4; ni++)
                    mma_f16(macc[mi][ni], (const uint32_t*)&a[mi], (const uint32_t*)&b[ni]);
        }
        if (++s >= 3) s -= 3;
    }

    // sc x2^6 * class x2^8 -> *2^-14
    const int lq = lane >> 2;
    const int ld = lane & 3;
    const float ds = 6.103515625e-05f;
    float* ob = out + (size_t)blockIdx.z * 4096 * 512;
#pragma unroll
    for (int mi = 0; mi < 4; mi++) {
        const int r = m0 + wm * 64 + mi * 16 + lq;
#pragma unroll
        for (int ni = 0; ni < 4; ni++) {
            const int c = n0 + wn * 32 + ni * 8 + 2 * ld;
            *(float2*)(ob + (size_t)r * 512 + c) =
                make_float2(macc[mi][ni][0] * ds, macc[mi][ni][1] * ds);
            *(float2*)(ob + (size_t)(r + 8) * 512 + c) =
                make_float2(macc[mi][ni][2] * ds, macc[mi][ni][3] * ds);
        }
    }
}

// ---------------------------------------------------------------------------
// Stage 2: fused bilinear + relu + score (128-d chunks, 3x64KB, 1 CTA/SM).
// ---------------------------------------------------------------------------
#define S2_SF 32768                       // halves per stage (A 16K + B 16K)
#define S2_SMEM (3 * S2_SF * 2)           // 196608 B

__global__ void __launch_bounds__(256, 1)
stage2_f16(const __half* __restrict__ q16, const __half* __restrict__ T16,
           const float* __restrict__ score_w, const float* __restrict__ score_b,
           float* __restrict__ other)
{
    extern __shared__ char smc[];
    __half* sm = (__half*)smc;
    const int tid = threadIdx.x;
    const int lane = tid & 31;
    const int wid = tid >> 5;
    const int wm = wid >> 2;
    const int wn = wid & 3;
    const int q0 = blockIdx.y * 128;
    const int c0 = blockIdx.x * 128;

    const size_t aBase = (size_t)(q0 >> 7) * 8 * 8192;
    const size_t bBase = (size_t)(c0 >> 7) * 8 * 8192;

    float sacc[4][4][4];
#pragma unroll
    for (int mi = 0; mi < 4; mi++)
#pragma unroll
        for (int ni = 0; ni < 4; ni++)
#pragma unroll
            for (int r = 0; r < 4; r++) sacc[mi][ni][r] = 0.0f;

    auto issue = [&](int it, int s) {
        const int k = it >> 2, t = it & 3;
        const __half* srcA = q16 + aBase + (size_t)t * 16384 + tid * 8;
        const __half* srcB = T16 + (size_t)k * 2097152 + bBase + (size_t)t * 16384 + tid * 8;
        uint32_t da = smem_u32(sm + s * S2_SF) + tid * 16;
        uint32_t db = da + 32768;
#pragma unroll
        for (int i = 0; i < 8; i++) {
            CPA(da + i * 4096, srcA + i * 2048);
            CPA(db + i * 4096, srcB + i * 2048);
        }
        CPA_COMMIT();
    };

    issue(0, 0);
    issue(1, 1);

    float macc[4][4][4];
    int s = 0;
#pragma unroll 1
    for (int it = 0; it < 32; it++) {
        const int k = it >> 2, t = it & 3;
        if (t == 0) {
#pragma unroll
            for (int mi = 0; mi < 4; mi++)
#pragma unroll
                for (int ni = 0; ni < 4; ni++)
#pragma unroll
                    for (int r = 0; r < 4; r++) macc[mi][ni][r] = 0.0f;
        }

        if (it < 31) CPA_WAIT1(); else CPA_WAIT0();
        __syncthreads();
        if (it + 2 < 32) {
            int s2 = s + 2; if (s2 >= 3) s2 -= 3;
            issue(it + 2, s2);
        }

        const __half* pa = sm + s * S2_SF;
        const __half* pb = pa + 16384;
#pragma unroll
        for (int kk = 0; kk < 8; kk++) {
            const int sub = (kk >> 2) * 8192;
            const int kf = kk & 3;
            uint4 a[4];
            uint2 b[4];
#pragma unroll
            for (int mi = 0; mi < 4; mi++)
                a[mi] = *(const uint4*)(pa + sub + (((wm * 4 + mi) * 4 + kf) << 8) + lane * 8);
#pragma unroll
            for (int ni = 0; ni < 4; ni++)
                b[ni] = *(const uint2*)(pb + sub + (((wn * 4 + ni) * 4 + kf) << 7) + lane * 4);
#pragma unroll
            for (int mi = 0; mi < 4; mi++)
#pragma unroll
                for (int ni = 0; ni < 4; ni++)
                    mma_f16(macc[mi][ni], (const uint32_t*)&a[mi], (const uint32_t*)&b[ni]);
        }

        if (t == 3) {
            // acc = P * 2^16 (q x2^8, T x2^8): fold 2^-16 into w
            const float w = __ldg(score_w + k) * 1.52587890625e-05f;
#pragma unroll
            for (int mi = 0; mi < 4; mi++)
#pragma unroll
                for (int ni = 0; ni < 4; ni++)
#pragma unroll
                    for (int r = 0; r < 4; r++)
                        sacc[mi][ni][r] = fmaf(fmaxf(macc[mi][ni][r], 0.0f), w,
                                               sacc[mi][ni][r]);
        }
        if (++s >= 3) s -= 3;
    }

    const int lq = lane >> 2;
    const int ld = lane & 3;
    const float sb = __ldg(score_b);
#pragma unroll
    for (int mi = 0; mi < 4; mi++) {
        const int q = q0 + wm * 64 + mi * 16 + lq;
#pragma unroll
        for (int ni = 0; ni < 4; ni++) {
            const int c = c0 + wn * 32 + ni * 8 + 2 * ld;
            *(float2*)(other + (size_t)q * 4096 + c) =
                make_float2(sb + sacc[mi][ni][0], sb + sacc[mi][ni][1]);
            *(float2*)(other + (size_t)(q + 8) * 4096 + c) =
                make_float2(sb + sacc[mi][ni][2], sb + sacc[mi][ni][3]);
        }
    }
}

// ---------------------------------------------------------------------------
// Softmax (paired rows q, q+8); fp16 A-pack output (Ktot=4096, x2^6).
// ---------------------------------------------------------------------------
__global__ void softmax_pack2(const float* __restrict__ o, __half* __restrict__ sc)
{
    const int b = blockIdx.x;
    const int qa = ((b >> 3) << 4) | (b & 7);
    const int tid = threadIdx.x;

    float v0[16], v1[16];
    {
        const float4* p0 = (const float4*)(o + (size_t)qa * 4096) + tid * 4;
        const float4* p1 = (const float4*)(o + (size_t)(qa + 8) * 4096) + tid * 4;
#pragma unroll
        for (int i = 0; i < 4; i++) {
            float4 x = p0[i];
            v0[i * 4] = x.x; v0[i * 4 + 1] = x.y; v0[i * 4 + 2] = x.z; v0[i * 4 + 3] = x.w;
            float4 y = p1[i];
            v1[i * 4] = y.x; v1[i * 4 + 1] = y.y; v1[i * 4 + 2] = y.z; v1[i * 4 + 3] = y.w;
        }
    }
    float mx0 = -1e30f, mx1 = -1e30f;
#pragma unroll
    for (int i = 0; i < 16; i++) { mx0 = fmaxf(mx0, v0[i]); mx1 = fmaxf(mx1, v1[i]); }

    __shared__ float sm0[8], sm1[8];
#pragma unroll
    for (int o2 = 16; o2 > 0; o2 >>= 1) {
        mx0 = fmaxf(mx0, __shfl_xor_sync(0xffffffffu, mx0, o2));
        mx1 = fmaxf(mx1, __shfl_xor_sync(0xffffffffu, mx1, o2));
    }
    if ((tid & 31) == 0) { sm0[tid >> 5] = mx0; sm1[tid >> 5] = mx1; }
    __syncthreads();
    mx0 = sm0[0]; mx1 = sm1[0];
#pragma unroll
    for (int i = 1; i < 8; i++) { mx0 = fmaxf(mx0, sm0[i]); mx1 = fmaxf(mx1, sm1[i]); }
    __syncthreads();

    float s0 = 0.0f, s1 = 0.0f;
#pragma unroll
    for (int i = 0; i < 16; i++) {
        v0[i] = expf(v0[i] - mx0); s0 += v0[i];
        v1[i] = expf(v1[i] - mx1); s1 += v1[i];
    }
#pragma unroll
    for (int o2 = 16; o2 > 0; o2 >>= 1) {
        s0 += __shfl_xor_sync(0xffffffffu, s0, o2);
        s1 += __shfl_xor_sync(0xffffffffu, s1, o2);
    }
    if ((tid & 31) == 0) { sm0[tid >> 5] = s0; sm1[tid >> 5] = s1; }
    __syncthreads();
    s0 = 0.0f; s1 = 0.0f;
#pragma unroll
    for (int i = 0; i < 8; i++) { s0 += sm0[i]; s1 += sm1[i]; }
    const float i0 = 64.0f / s0, i1 = 64.0f / s1;   // fold x2^6 scale

    __half hbuf[32];
#pragma unroll
    for (int j = 0; j < 32; j++) {
        int t2 = j >> 3, kb3 = (j >> 2) & 1, mrow = (j >> 1) & 1, h = j & 1;
        int kl = kb3 * 8 + t2 * 2 + h;
        hbuf[j] = __float2half_rn(mrow ? v1[kl] * i1 : v0[kl] * i0);
    }
    __half* dst = sc + apack16(qa, tid * 16, 4096);
#pragma unroll
    for (int j = 0; j < 4; j++)
        *(uint4*)(dst + j * 8) = *(const uint4*)(hbuf + j * 8);
}

// ---------------------------------------------------------------------------
// Fused stage 5: qf = query + sum_z qfp[z] (smem), out = tanh(qf @ hwT + b).
// ---------------------------------------------------------------------------
__global__ void __launch_bounds__(256, 2)
stage5_fused(const float* __restrict__ query, const float* __restrict__ qfp,
             const float* __restrict__ hwT, const float* __restrict__ hash_b,
             float* __restrict__ out)
{
    __shared__ float qf_s[16 * 512];
    const int tid = threadIdx.x;
    const int qbase = blockIdx.x * 16;
    const size_t S = (size_t)4096 * 512;
    const size_t gbase = (size_t)qbase * 512;

#pragma unroll
    for (int j = 0; j < 8; j++) {
        int i4 = tid + j * 256;
        size_t g = gbase + (size_t)i4 * 4;
        float4 acc = *(const float4*)(query + g);
#pragma unroll
        for (int z = 0; z < 8; z++) {
            float4 p = *(const float4*)(qfp + z * S + g);
            acc.x += p.x; acc.y += p.y; acc.z += p.z; acc.w += p.w;
        }
        *(float4*)(qf_s + i4 * 4) = acc;
    }
    __syncthreads();

    const int q = tid >> 4;
    const int lb = (tid & 15) * 4;
    float a0 = 0, a1 = 0, a2 = 0, a3 = 0;
    const float* qr = qf_s + q * 512;
#pragma unroll 4
    for (int d = 0; d < 512; d += 4) {
        float4 qv = *(const float4*)(qr + d);
        float4 h0 = __ldg((const float4*)(hwT + (size_t)d * 64 + lb));
        float4 h1 = __ldg((const float4*)(hwT + (size_t)(d + 1) * 64 + lb));
        float4 h2 = __ldg((const float4*)(hwT + (size_t)(d + 2) * 64 + lb));
        float4 h3 = __ldg((const float4*)(hwT + (size_t)(d + 3) * 64 + lb));
        a0 = fmaf(qv.x, h0.x, fmaf(qv.y, h1.x, fmaf(qv.z, h2.x, fmaf(qv.w, h3.x, a0))));
        a1 = fmaf(qv.x, h0.y, fmaf(qv.y, h1.y, fmaf(qv.z, h2.y, fmaf(qv.w, h3.y, a1))));
        a2 = fmaf(qv.x, h0.z, fmaf(qv.y, h1.z, fmaf(qv.z, h2.z, fmaf(qv.w, h3.z, a2))));
        a3 = fmaf(qv.x, h0.w, fmaf(qv.y, h1.w, fmaf(qv.z, h2.w, fmaf(qv.w, h3.w, a3))));
    }
    float4 hb = __ldg((const float4*)(hash_b + lb));
    float4 r = make_float4(tanhf(a0 + hb.x), tanhf(a1 + hb.y),
                           tanhf(a2 + hb.z), tanhf(a3 + hb.w));
    *(float4*)(out + (size_t)(qbase + q) * 64 + lb) = r;
}

// ---------------------------------------------------------------------------
// Prep kernels
// ---------------------------------------------------------------------------
__global__ void transpose_hw(const float* __restrict__ hw)
{
    int idx = blockIdx.x * blockDim.x + threadIdx.x;
    int l = idx >> 9;
    int d = idx & 511;
    g_hwT[d * 64 + l] = hw[idx];
}

// Merged A-side pack: blocks 0-255 -> q16 (single x2^8),
// blocks 256-511 -> class A hi/lo (x2^8). One launch (keeps stage2 at slot #4).
__global__ void pack_qcA(const float* __restrict__ q, const float* __restrict__ cv)
{
    const int blk = blockIdx.x;
    const bool doClass = (blk >= 256);
    const float* src = doClass ? cv : q;
    int t = (blk & 255) * 256 + threadIdx.x;
    int kg = t & 31;
    int pr = t >> 5;
    int m0 = ((pr >> 3) << 4) | (pr & 7);
    int kb = kg * 16;

    float v0[16], v1[16];
    const float4* p0 = (const float4*)(src + (size_t)m0 * 512 + kb);
    const float4* p1 = (const float4*)(src + (size_t)(m0 + 8) * 512 + kb);
#pragma unroll
    for (int i = 0; i < 4; i++) {
        float4 x = p0[i];
        v0[i*4] = x.x; v0[i*4+1] = x.y; v0[i*4+2] = x.z; v0[i*4+3] = x.w;
        float4 y = p1[i];
        v1[i*4] = y.x; v1[i*4+1] = y.y; v1[i*4+2] = y.z; v1[i*4+3] = y.w;
    }
    size_t off = apack16(m0, kb, 512);
    if (!doClass) {
        __half hbuf[32];
#pragma unroll
        for (int j = 0; j < 32; j++) {
            int t2 = j >> 3, kb3 = (j >> 2) & 1, mrow = (j >> 1) & 1, h = j & 1;
            int kl = kb3 * 8 + t2 * 2 + h;
            hbuf[j] = __float2half_rn((mrow ? v1[kl] : v0[kl]) * 256.0f);
        }
#pragma unroll
        for (int j = 0; j < 4; j++)
            *(uint4*)(g_q16 + off + j * 8) = *(const uint4*)(hbuf + j * 8);
    } else {
        __half hb[32], lb[32];
#pragma unroll
        for (int j = 0; j < 32; j++) {
            int t2 = j >> 3, kb3 = (j >> 2) & 1, mrow = (j >> 1) & 1, h = j & 1;
            int kl = kb3 * 8 + t2 * 2 + h;
            float v = (mrow ? v1[kl] : v0[kl]) * 256.0f;
            __half hi = __float2half_rn(v);
            hb[j] = hi;
            lb[j] = __float2half_rn(v - __half2float(hi));
        }
#pragma unroll
        for (int j = 0; j < 4; j++) {
            *(uint4*)(g_cah + off + j * 8) = *(const uint4*)(hb + j * 8);
            *(uint4*)(g_cal + off + j * 8) = *(const uint4*)(lb + j * 8);
        }
    }
}

// in [R][C] (R=k-dim, C=n-dim) -> B-pack fp16 hi/lo, one thread per 16-k group.
__global__ void pack_B16_split(const float* __restrict__ in,
                               __half* __restrict__ ohi, __half* __restrict__ olo,
                               int R, int C, float scale)
{
    unsigned tt = blockIdx.x * blockDim.x + threadIdx.x;
    unsigned k16 = tt / (unsigned)C;
    unsigned n = tt - k16 * (unsigned)C;
    int kb = (int)k16 * 16;

    unsigned short h[16], l[16];
#pragma unroll
    for (int i = 0; i < 16; i++) {
        float v = in[(size_t)(kb + i) * C + n] * scale;
        __half hv = __float2half_rn(v);
        h[i] = __half_as_ushort(hv);
        l[i] = __half_as_ushort(__float2half_rn(v - __half2float(hv)));
    }
    size_t base = bpack16((int)n, kb, R);
    const int map[16] = {0,1,8,9,2,3,10,11,4,5,12,13,6,7,14,15};
    uint32_t uh[8], ul[8];
#pragma unroll
    for (int j = 0; j < 8; j++) {
        uh[j] = (uint32_t)h[map[2*j]] | ((uint32_t)h[map[2*j+1]] << 16);
        ul[j] = (uint32_t)l[map[2*j]] | ((uint32_t)l[map[2*j+1]] << 16);
    }
    *(uint4*)(ohi + base)     = make_uint4(uh[0], uh[1], uh[2], uh[3]);
    *(uint4*)(ohi + base + 8) = make_uint4(uh[4], uh[5], uh[6], uh[7]);
    *(uint4*)(olo + base)     = make_uint4(ul[0], ul[1], ul[2], ul[3]);
    *(uint4*)(olo + base + 8) = make_uint4(ul[4], ul[5], ul[6], ul[7]);
}

// in [R][C] -> B-pack fp16 single (for class^T)
__global__ void pack_B16(const float* __restrict__ in, __half* __restrict__ outp,
                         int R, int C, float scale)
{
    unsigned tt = blockIdx.x * blockDim.x + threadIdx.x;
    unsigned k16 = tt / (unsigned)C;
    unsigned n = tt - k16 * (unsigned)C;
    int kb = (int)k16 * 16;

    unsigned short h[16];
#pragma unroll
    for (int i = 0; i < 16; i++)
        h[i] = __half_as_ushort(__float2half_rn(in[(size_t)(kb + i) * C + n] * scale));
    size_t base = bpack16((int)n, kb, R);
    const int map[16] = {0,1,8,9,2,3,10,11,4,5,12,13,6,7,14,15};
    uint32_t u[8];
#pragma unroll
    for (int j = 0; j < 8; j++)
        u[j] = (uint32_t)h[map[2*j]] | ((uint32_t)h[map[2*j+1]] << 16);
    *(uint4*)(outp + base)     = make_uint4(u[0], u[1], u[2], u[3]);
    *(uint4*)(outp + base + 8) = make_uint4(u[4], u[5], u[6], u[7]);
}

// ---------------------------------------------------------------------------
extern "C" void kernel_launch(void* const* d_in, const int* in_sizes, int n_in,
                              void* d_out, int out_size)
{
    const float* class_v = (const float*)d_in[0];
    const float* query_v = (const float*)d_in[1];
    const float* Mmat    = (const float*)d_in[2];
    const float* score_w = (const float*)d_in[3];
    const float* score_b = (const float*)d_in[4];
    const float* hash_w  = (const float*)d_in[5];
    const float* hash_b  = (const float*)d_in[6];
    float* out = (float*)d_out;

    float *other, *qfp, *hwT;
    __half *T16, *sc16, *q16, *cah, *cal, *mbh, *mbl, *cbh;
    cudaGetSymbolAddress((void**)&T16, g_T16);
    cudaGetSymbolAddress((void**)&other, g_other);
    cudaGetSymbolAddress((void**)&sc16, g_sc16);
    cudaGetSymbolAddress((void**)&q16, g_q16);
    cudaGetSymbolAddress((void**)&cah, g_cah);
    cudaGetSymbolAddress((void**)&cal, g_cal);
    cudaGetSymbolAddress((void**)&mbh, g_mbh);
    cudaGetSymbolAddress((void**)&mbl, g_mbl);
    cudaGetSymbolAddress((void**)&cbh, g_cbh);
    cudaGetSymbolAddress((void**)&qfp, g_qfp);
    cudaGetSymbolAddress((void**)&hwT, g_hwT);

    const int SM96 = 3 * 32768;    // 98304 B  (2 CTAs/SM)
    cudaFuncSetAttribute(gemm_split_f16, cudaFuncAttributeMaxDynamicSharedMemorySize, SM96);
    cudaFuncSetAttribute(gemm_single_f16, cudaFuncAttributeMaxDynamicSharedMemorySize, SM96);
    cudaFuncSetAttribute(stage2_f16, cudaFuncAttributeMaxDynamicSharedMemorySize, S2_SMEM);

    // 1: merged A-side packs (q16 + class hi/lo)
    pack_qcA<<<512, 256>>>(query_v, class_v);
    // 2: M -> B-pack hi/lo (x2^10)
    pack_B16_split<<<512, 256>>>(Mmat, mbh, mbl, 512, 4096, 1024.0f);
    // 3: Stage 1: T = class @ M  (fp16 3-MMA split, 2 CTAs/SM, staged epilogue)
    gemm_split_f16<<<dim3(32, 32), 256, SM96>>>(cah, cal, mbh, mbl, T16);
    // 4: Stage 2 (profiled slot): fused bilinear + relu + score
    stage2_f16<<<dim3(32, 32), 256, S2_SMEM>>>(q16, T16, score_w, score_b, other);
    // 5: class^T -> B-pack (x2^8)
    pack_B16<<<512, 256>>>(class_v, cbh, 4096, 512, 256.0f);
    // 6: softmax -> fp16 packed scores
    softmax_pack2<<<2048, 256>>>(other, sc16);
    // 7: Stage 4: qf partials = sc @ class (split-K=8, 2 CTAs/SM)
    gemm_single_f16<<<dim3(4, 32, 8), 256, SM96>>>(sc16, cbh, qfp, 4096, 512);
    // 8: hash_w transpose
    transpose_hw<<<128, 256>>>(hash_w);
    // 9: Stage 5 (fused reduce + residual + tanh GEMM)
    stage5_fused<<<256, 256>>>(query_v, qfp, hwT, hash_b, out);
}